// round 10
// baseline (speedup 1.0000x reference)
#include <cuda_runtime.h>
#include <cuda_bf16.h>
#include <cstdint>

typedef __nv_bfloat16 bf16;

// ---------------------------------------------------------------------------
// Static scratch
// ---------------------------------------------------------------------------
__device__ __align__(1024) bf16 g_zh [(size_t)2048 * 16640];
__device__ __align__(1024) bf16 g_zl [(size_t)2048 * 16640];
__device__ __align__(1024) float g_f1[(size_t)2048 * 1024];
__device__ __align__(1024) float g_s0[2048 * 64];
__device__ __align__(1024) bf16 g_wah[64 * 64],   g_wal[64 * 64];
__device__ __align__(1024) bf16 g_w1h[128 * 192], g_w1l[128 * 192];
__device__ __align__(1024) bf16 g_w2h[256 * 384], g_w2l[256 * 384];
__device__ __align__(1024) bf16 g_w3h[256 * 768], g_w3l[256 * 768];
__device__ __align__(1024) bf16 g_wfh[(size_t)1024 * 16640];
__device__ __align__(1024) bf16 g_wfl[(size_t)1024 * 16640];
__device__ __align__(1024) float g_wpt [64 * 64];
__device__ __align__(1024) float g_wb1t[64 * 64];
__device__ __align__(1024) float g_wb2t[64 * 128];
__device__ __align__(1024) float g_wb3t[128 * 256];

// ---------------------------------------------------------------------------
// Helpers
// ---------------------------------------------------------------------------
__device__ __forceinline__ uint32_t cvta_smem(const void* p) {
    return (uint32_t)__cvta_generic_to_shared(p);
}
__device__ __forceinline__ void cpa16(uint32_t dst, const void* src, int sz) {
    asm volatile("cp.async.cg.shared.global [%0], [%1], 16, %2;"
                 :: "r"(dst), "l"(src), "r"(sz) : "memory");
}
__device__ __forceinline__ void cp_commit() {
    asm volatile("cp.async.commit_group;" ::: "memory");
}
#define CP_WAIT1() asm volatile("cp.async.wait_group 1;" ::: "memory")
#define CP_WAIT0() asm volatile("cp.async.wait_group 0;" ::: "memory")
#define LDM4(r, addr)                                                         \
    asm volatile("ldmatrix.sync.aligned.m8n8.x4.shared.b16 "                  \
                 "{%0,%1,%2,%3}, [%4];"                                       \
                 : "=r"((r)[0]), "=r"((r)[1]), "=r"((r)[2]), "=r"((r)[3])     \
                 : "r"(addr))

__device__ __forceinline__ void mma16816(float* d, const uint32_t* a,
                                         uint32_t b0, uint32_t b1) {
    asm volatile(
        "mma.sync.aligned.m16n8k16.row.col.f32.bf16.bf16.f32 "
        "{%0,%1,%2,%3}, {%4,%5,%6,%7}, {%8,%9}, {%0,%1,%2,%3};"
        : "+f"(d[0]), "+f"(d[1]), "+f"(d[2]), "+f"(d[3])
        : "r"(a[0]), "r"(a[1]), "r"(a[2]), "r"(a[3]), "r"(b0), "r"(b1));
}
__device__ __forceinline__ void split2(float v, bf16& h, bf16& l) {
    h = __float2bfloat16(v);
    l = __float2bfloat16(v - __bfloat162float(h));
}
__device__ __forceinline__ uint32_t pack2(bf16 a, bf16 b) {
    return (uint32_t)__bfloat16_as_ushort(a) |
           ((uint32_t)__bfloat16_as_ushort(b) << 16);
}
#define MMA3(acc0, acc1, AH, AL, BH, BL)                                      \
    mma16816(acc0, AH, BH[0], BH[2]); mma16816(acc1, AH, BH[1], BH[3]);       \
    mma16816(acc0, AH, BL[0], BL[2]); mma16816(acc1, AH, BL[1], BL[3]);       \
    mma16816(acc0, AL, BH[0], BH[2]); mma16816(acc1, AL, BH[1], BH[3]);

// ---------------------------------------------------------------------------
// Fused per-batch conv chain: x -> stageA -> conv1 -> conv2 -> conv3 -> z
// 2048 CTAs x 256 threads. SMEM regions (byte offsets from dynamic base):
//  P0: h0 (258 rows x 144B x 2 planes) ... later conv2/3 weight dbl-buffers
//  P1: xA (256x144 x2) + wa (64x144 x2) + conv1 W bufs ... later h1 (even/odd
//      272B rows) ... later h2 (even/odd 528B rows)
// ---------------------------------------------------------------------------
#define P0 0u
#define P1 81920u
#define XA_H (P1 + 0u)
#define XA_L (P1 + 36864u)
#define WA_H (P1 + 73728u)
#define WA_L (P1 + 82944u)
#define C1B(t) (P1 + 73728u + (uint32_t)(t) * 20480u)
#define H0_H (P0 + 0u)
#define H0_L (P0 + 37152u)
#define C23B(t) (P0 + (uint32_t)(t) * 40960u)
#define H1_H (P1 + 0u)
#define H1_L (P1 + 69904u)
#define H1_ODD 35088u
#define H2_H (P1 + 0u)
#define H2_L (P1 + 68640u)
#define H2_ODD 34320u
#define FUSED_SMEM 221728

__global__ void __launch_bounds__(256, 1) fused_conv_kernel(
    const float* __restrict__ x, const float* __restrict__ s0g,
    const bf16* __restrict__ wah, const bf16* __restrict__ wal,
    const bf16* __restrict__ w1h, const bf16* __restrict__ w1l,
    const bf16* __restrict__ w2h, const bf16* __restrict__ w2l,
    const bf16* __restrict__ w3h, const bf16* __restrict__ w3l,
    const float* __restrict__ b1, const float* __restrict__ b2,
    const float* __restrict__ b3,
    bf16* __restrict__ zh, bf16* __restrict__ zl)
{
    extern __shared__ __align__(1024) char smem_c[];
    const uint32_t S = cvta_smem(smem_c);
    const int tid = threadIdx.x;
    const int lane = tid & 31;
    const int wid = tid >> 5;
    const int b = blockIdx.x;
    const int laneM = lane & 15;
    const uint32_t laneK = (uint32_t)(lane >> 4) << 4;
    const int tr = lane >> 2;
    const int tc = (lane & 3) * 2;
    const float* xb = x + (size_t)b * 16384;

    // ===== load xA (split) + wa =========================================
    #pragma unroll
    for (int t = 0; t < 16; ++t) {
        int idx = tid + t * 256;
        int row = idx >> 4, q = idx & 15;
        uint32_t off = (uint32_t)row * 144 + (uint32_t)q * 8;
        if (row < 255) {
            float4 v = *reinterpret_cast<const float4*>(xb + (row + 1) * 64 + q * 4);
            bf16 h0, h1, h2, h3, l0, l1, l2, l3;
            split2(v.x, h0, l0); split2(v.y, h1, l1);
            split2(v.z, h2, l2); split2(v.w, h3, l3);
            *reinterpret_cast<uint2*>(smem_c + XA_H + off) =
                make_uint2(pack2(h0, h1), pack2(h2, h3));
            *reinterpret_cast<uint2*>(smem_c + XA_L + off) =
                make_uint2(pack2(l0, l1), pack2(l2, l3));
        } else {
            *reinterpret_cast<uint2*>(smem_c + XA_H + off) = make_uint2(0u, 0u);
            *reinterpret_cast<uint2*>(smem_c + XA_L + off) = make_uint2(0u, 0u);
        }
    }
    #pragma unroll
    for (int t = 0; t < 4; ++t) {
        int idx = tid + t * 256;
        int plane = idx >> 9, v = idx & 511;
        int n = v >> 3, q = v & 7;
        const bf16* src = (plane ? wal : wah) + n * 64 + q * 8;
        cpa16(S + (plane ? WA_L : WA_H) + (uint32_t)n * 144 + (uint32_t)q * 16,
              src, 16);
    }
    cp_commit(); CP_WAIT0();
    __syncthreads();

    // ===== Stage A: M=256(255) N=64 K=64; warps 4M x 2N =================
    {
        const int m0w = (wid >> 1) * 64;
        const int n0w = (wid & 1) * 32;
        float acc[4][4][4] = {};
        #pragma unroll
        for (int ks = 0; ks < 4; ++ks) {
            uint32_t ah[4][4], al[4][4];
            #pragma unroll
            for (int mt = 0; mt < 4; ++mt) {
                uint32_t ra = (uint32_t)(m0w + mt * 16 + laneM) * 144 +
                              (uint32_t)ks * 32 + laneK;
                LDM4(ah[mt], S + XA_H + ra);
                LDM4(al[mt], S + XA_L + ra);
            }
            #pragma unroll
            for (int c = 0; c < 2; ++c) {
                uint32_t rb = (uint32_t)(n0w + c * 16 + laneM) * 144 +
                              (uint32_t)ks * 32 + laneK;
                uint32_t bh[4], bl[4];
                LDM4(bh, S + WA_H + rb);
                LDM4(bl, S + WA_L + rb);
                #pragma unroll
                for (int mt = 0; mt < 4; ++mt) {
                    MMA3(acc[mt][2 * c], acc[mt][2 * c + 1], ah[mt], al[mt], bh, bl);
                }
            }
        }
        __syncthreads();
        #pragma unroll
        for (int mt = 0; mt < 4; ++mt)
            #pragma unroll
            for (int half = 0; half < 2; ++half) {
                int m = m0w + mt * 16 + tr + half * 8;
                if (m < 255) {
                    #pragma unroll
                    for (int nt = 0; nt < 4; ++nt) {
                        int n = n0w + nt * 8 + tc;
                        float v0 = fmaxf(acc[mt][nt][half * 2 + 0] + s0g[b * 64 + n], 0.f);
                        float v1 = fmaxf(acc[mt][nt][half * 2 + 1] + s0g[b * 64 + n + 1], 0.f);
                        bf16 h0v, h1v, l0v, l1v;
                        split2(v0, h0v, l0v); split2(v1, h1v, l1v);
                        uint32_t off = (uint32_t)(m + 1) * 144 + (uint32_t)n * 2;
                        *reinterpret_cast<uint32_t*>(smem_c + H0_H + off) = pack2(h0v, h1v);
                        *reinterpret_cast<uint32_t*>(smem_c + H0_L + off) = pack2(l0v, l1v);
                    }
                }
            }
        if (tid < 96) {   // zero h0 halo rows 0, 256, 257
            int rs = tid >> 5, q = tid & 31;
            uint32_t rr = (rs == 0) ? 0u : (rs == 1 ? 256u : 257u);
            uint32_t off = rr * 144 + (uint32_t)q * 4;
            *reinterpret_cast<uint32_t*>(smem_c + H0_H + off) = 0u;
            *reinterpret_cast<uint32_t*>(smem_c + H0_L + off) = 0u;
        }
        __syncthreads();
    }

    // ===== Conv1: M=256(255) N=128 K=192; warps 4M x 2N =================
    {
        const int m0w = (wid >> 1) * 64;
        const int n0w = (wid & 1) * 64;
        float acc[4][8][4] = {};
        auto loadB = [&](int t, int buf) {
            int j = t >> 1, c32 = t & 1;
            #pragma unroll
            for (int r4 = 0; r4 < 4; ++r4) {
                int idx = tid + r4 * 256;
                int plane = idx >> 9, v = idx & 511;
                int n = v >> 2, q = v & 3;
                const bf16* src = (plane ? w1l : w1h) + n * 192 + j * 64 + c32 * 32 + q * 8;
                cpa16(S + C1B(buf) + (uint32_t)plane * 10240u +
                      (uint32_t)n * 80 + (uint32_t)q * 16, src, 16);
            }
        };
        loadB(0, 0); cp_commit();
        #pragma unroll 1
        for (int t = 0; t < 6; ++t) {
            if (t < 5) { loadB(t + 1, (t + 1) & 1); cp_commit(); CP_WAIT1(); }
            else       { CP_WAIT0(); }
            __syncthreads();
            const int j = t >> 1, c32 = t & 1;
            const uint32_t bB = C1B(t & 1);
            #pragma unroll
            for (int ks = 0; ks < 2; ++ks) {
                uint32_t ah[4][4], al[4][4];
                #pragma unroll
                for (int mt = 0; mt < 4; ++mt) {
                    uint32_t ra = (uint32_t)(m0w + mt * 16 + laneM + j) * 144 +
                                  (uint32_t)(c32 * 64 + ks * 32) + laneK;
                    LDM4(ah[mt], S + H0_H + ra);
                    LDM4(al[mt], S + H0_L + ra);
                }
                #pragma unroll
                for (int c = 0; c < 4; ++c) {
                    uint32_t rb = (uint32_t)(n0w + c * 16 + laneM) * 80 +
                                  (uint32_t)ks * 32 + laneK;
                    uint32_t bh[4], bl[4];
                    LDM4(bh, S + bB + rb);
                    LDM4(bl, S + bB + 10240u + rb);
                    #pragma unroll
                    for (int mt = 0; mt < 4; ++mt) {
                        MMA3(acc[mt][2 * c], acc[mt][2 * c + 1], ah[mt], al[mt], bh, bl);
                    }
                }
            }
            __syncthreads();
        }
        #pragma unroll
        for (int mt = 0; mt < 4; ++mt)
            #pragma unroll
            for (int half = 0; half < 2; ++half) {
                int m = m0w + mt * 16 + tr + half * 8;
                if (m < 255) {
                    uint32_t rr = (uint32_t)(m + 1);
                    uint32_t base = ((rr & 1) ? H1_ODD : 0u) + (rr >> 1) * 272;
                    #pragma unroll
                    for (int nt = 0; nt < 8; ++nt) {
                        int n = n0w + nt * 8 + tc;
                        float v0 = fmaxf(acc[mt][nt][half * 2 + 0] + b1[n], 0.f);
                        float v1 = fmaxf(acc[mt][nt][half * 2 + 1] + b1[n + 1], 0.f);
                        bf16 h0v, h1v, l0v, l1v;
                        split2(v0, h0v, l0v); split2(v1, h1v, l1v);
                        uint32_t off = base + (uint32_t)n * 2;
                        *reinterpret_cast<uint32_t*>(smem_c + H1_H + off) = pack2(h0v, h1v);
                        *reinterpret_cast<uint32_t*>(smem_c + H1_L + off) = pack2(l0v, l1v);
                    }
                }
            }
        if (tid < 128) {  // zero h1 halo rows 0, 256
            int rs = tid >> 6, q = tid & 63;
            uint32_t rr = rs ? 256u : 0u;
            uint32_t off = ((rr & 1) ? H1_ODD : 0u) + (rr >> 1) * 272 + (uint32_t)q * 4;
            *reinterpret_cast<uint32_t*>(smem_c + H1_H + off) = 0u;
            *reinterpret_cast<uint32_t*>(smem_c + H1_L + off) = 0u;
        }
        __syncthreads();
    }

    // ===== Conv2: M=128 N=256 K=384 stride2; warps 2M x 4N ==============
    {
        const int m0w = (wid >> 2) * 64;
        const int n0w = (wid & 3) * 64;
        float acc[4][8][4] = {};
        auto loadB = [&](int t, int buf) {
            int j = t >> 2, c32 = t & 3;
            #pragma unroll
            for (int r4 = 0; r4 < 8; ++r4) {
                int idx = tid + r4 * 256;
                int plane = idx >> 10, v = idx & 1023;
                int n = v >> 2, q = v & 3;
                const bf16* src = (plane ? w2l : w2h) + n * 384 + j * 128 + c32 * 32 + q * 8;
                cpa16(S + C23B(buf) + (uint32_t)plane * 20480u +
                      (uint32_t)n * 80 + (uint32_t)q * 16, src, 16);
            }
        };
        loadB(0, 0); cp_commit();
        #pragma unroll 1
        for (int t = 0; t < 12; ++t) {
            if (t < 11) { loadB(t + 1, (t + 1) & 1); cp_commit(); CP_WAIT1(); }
            else        { CP_WAIT0(); }
            __syncthreads();
            const int j = t >> 2, c32 = t & 3;
            const uint32_t bB = C23B(t & 1);
            const uint32_t sel = (uint32_t)(j & 1) * H1_ODD;
            const int jdiv = j >> 1;
            #pragma unroll
            for (int ks = 0; ks < 2; ++ks) {
                uint32_t ah[4][4], al[4][4];
                #pragma unroll
                for (int mt = 0; mt < 4; ++mt) {
                    uint32_t ra = sel + (uint32_t)(m0w + mt * 16 + laneM + jdiv) * 272 +
                                  (uint32_t)(c32 * 64 + ks * 32) + laneK;
                    LDM4(ah[mt], S + H1_H + ra);
                    LDM4(al[mt], S + H1_L + ra);
                }
                #pragma unroll
                for (int c = 0; c < 4; ++c) {
                    uint32_t rb = (uint32_t)(n0w + c * 16 + laneM) * 80 +
                                  (uint32_t)ks * 32 + laneK;
                    uint32_t bh[4], bl[4];
                    LDM4(bh, S + bB + rb);
                    LDM4(bl, S + bB + 20480u + rb);
                    #pragma unroll
                    for (int mt = 0; mt < 4; ++mt) {
                        MMA3(acc[mt][2 * c], acc[mt][2 * c + 1], ah[mt], al[mt], bh, bl);
                    }
                }
            }
            __syncthreads();
        }
        #pragma unroll
        for (int mt = 0; mt < 4; ++mt)
            #pragma unroll
            for (int half = 0; half < 2; ++half) {
                int m = m0w + mt * 16 + tr + half * 8;
                uint32_t rr = (uint32_t)(m + 1);
                uint32_t base = ((rr & 1) ? H2_ODD : 0u) + (rr >> 1) * 528;
                #pragma unroll
                for (int nt = 0; nt < 8; ++nt) {
                    int n = n0w + nt * 8 + tc;
                    float v0 = fmaxf(acc[mt][nt][half * 2 + 0] + b2[n], 0.f);
                    float v1 = fmaxf(acc[mt][nt][half * 2 + 1] + b2[n + 1], 0.f);
                    bf16 h0v, h1v, l0v, l1v;
                    split2(v0, h0v, l0v); split2(v1, h1v, l1v);
                    uint32_t off = base + (uint32_t)n * 2;
                    *reinterpret_cast<uint32_t*>(smem_c + H2_H + off) = pack2(h0v, h1v);
                    *reinterpret_cast<uint32_t*>(smem_c + H2_L + off) = pack2(l0v, l1v);
                }
            }
        {   // zero h2 halo rows 0, 129
            int rs = tid >> 7, q = tid & 127;
            uint32_t rr = rs ? 129u : 0u;
            uint32_t off = ((rr & 1) ? H2_ODD : 0u) + (rr >> 1) * 528 + (uint32_t)q * 4;
            *reinterpret_cast<uint32_t*>(smem_c + H2_H + off) = 0u;
            *reinterpret_cast<uint32_t*>(smem_c + H2_L + off) = 0u;
        }
        __syncthreads();
    }

    // ===== Conv3: M=64 N=256 K=768 stride2; warps 1M x 8N ===============
    {
        const int n0w = wid * 32;
        float acc[4][4][4] = {};
        auto loadB = [&](int t, int buf) {
            int j = t >> 3, c32 = t & 7;
            #pragma unroll
            for (int r4 = 0; r4 < 8; ++r4) {
                int idx = tid + r4 * 256;
                int plane = idx >> 10, v = idx & 1023;
                int n = v >> 2, q = v & 3;
                const bf16* src = (plane ? w3l : w3h) + n * 768 + j * 256 + c32 * 32 + q * 8;
                cpa16(S + C23B(buf) + (uint32_t)plane * 20480u +
                      (uint32_t)n * 80 + (uint32_t)q * 16, src, 16);
            }
        };
        loadB(0, 0); cp_commit();
        #pragma unroll 1
        for (int t = 0; t < 24; ++t) {
            if (t < 23) { loadB(t + 1, (t + 1) & 1); cp_commit(); CP_WAIT1(); }
            else        { CP_WAIT0(); }
            __syncthreads();
            const int j = t >> 3, c32 = t & 7;
            const uint32_t bB = C23B(t & 1);
            const uint32_t sel = (uint32_t)(j & 1) * H2_ODD;
            const int jdiv = j >> 1;
            #pragma unroll
            for (int ks = 0; ks < 2; ++ks) {
                uint32_t ah[4][4], al[4][4];
                #pragma unroll
                for (int mt = 0; mt < 4; ++mt) {
                    uint32_t ra = sel + (uint32_t)(mt * 16 + laneM + jdiv) * 528 +
                                  (uint32_t)(c32 * 64 + ks * 32) + laneK;
                    LDM4(ah[mt], S + H2_H + ra);
                    LDM4(al[mt], S + H2_L + ra);
                }
                #pragma unroll
                for (int c = 0; c < 2; ++c) {
                    uint32_t rb = (uint32_t)(n0w + c * 16 + laneM) * 80 +
                                  (uint32_t)ks * 32 + laneK;
                    uint32_t bh[4], bl[4];
                    LDM4(bh, S + bB + rb);
                    LDM4(bl, S + bB + 20480u + rb);
                    #pragma unroll
                    for (int mt = 0; mt < 4; ++mt) {
                        MMA3(acc[mt][2 * c], acc[mt][2 * c + 1], ah[mt], al[mt], bh, bl);
                    }
                }
            }
            __syncthreads();
        }
        bf16* zhb = zh + (size_t)b * 16640;
        bf16* zlb = zl + (size_t)b * 16640;
        #pragma unroll
        for (int mt = 0; mt < 4; ++mt)
            #pragma unroll
            for (int half = 0; half < 2; ++half) {
                int m = mt * 16 + tr + half * 8;
                #pragma unroll
                for (int nt = 0; nt < 4; ++nt) {
                    int n = n0w + nt * 8 + tc;
                    float v0 = fmaxf(acc[mt][nt][half * 2 + 0] + b3[n], 0.f);
                    float v1 = fmaxf(acc[mt][nt][half * 2 + 1] + b3[n + 1], 0.f);
                    bf16 h0v, h1v, l0v, l1v;
                    split2(v0, h0v, l0v); split2(v1, h1v, l1v);
                    *reinterpret_cast<uint32_t*>(zhb + m * 256 + n) = pack2(h0v, h1v);
                    *reinterpret_cast<uint32_t*>(zlb + m * 256 + n) = pack2(l0v, l1v);
                }
            }
    }
}

// ---------------------------------------------------------------------------
// fc1: 128x128 tiles, BK=64, warps 2M x 4N (validated template, fc1-only)
// ---------------------------------------------------------------------------
__global__ void __launch_bounds__(256, 1)
fc1_kernel(const bf16* __restrict__ Ahi, const bf16* __restrict__ Alo,
           const bf16* __restrict__ Whi, const bf16* __restrict__ Wlo,
           const float* __restrict__ bias, float* __restrict__ Of32)
{
    constexpr int KTOT = 16640, NITER = 260;
    constexpr int ASZ = 128 * 128, BSZ = 128 * 128, BUFB = 2 * ASZ + 2 * BSZ;
    extern __shared__ __align__(1024) char smem_c[];
    const uint32_t smem0 = cvta_smem(smem_c);
    const int tid = threadIdx.x;
    const int lane = tid & 31;
    const int wid = tid >> 5;
    const int warpM = wid >> 2, warpN = wid & 3;
    const int n0 = blockIdx.x * 128, m0 = blockIdx.y * 128;

    float acc[4][4][4] = {};
    auto load_tiles = [&](int it, int buf) {
        const int k0 = it * 64;
        const uint32_t sb = smem0 + buf * BUFB;
        #pragma unroll
        for (int rep = 0; rep < 4; ++rep) {
            int v = tid + rep * 256;
            int row = v >> 3, q = v & 7;
            size_t off = (size_t)(m0 + row) * KTOT + k0 + q * 8;
            uint32_t so = row * 128 + ((q * 16) ^ ((row & 7) << 4));
            cpa16(sb + so, Ahi + off, 16);
            cpa16(sb + ASZ + so, Alo + off, 16);
        }
        #pragma unroll
        for (int rep = 0; rep < 4; ++rep) {
            int v = tid + rep * 256;
            int n = v >> 3, q = v & 7;
            size_t off = (size_t)(n0 + n) * KTOT + k0 + q * 8;
            uint32_t so = n * 128 + ((q * 16) ^ ((n & 7) << 4));
            cpa16(sb + 2 * ASZ + so, Whi + off, 16);
            cpa16(sb + 2 * ASZ + BSZ + so, Wlo + off, 16);
        }
    };
    load_tiles(0, 0); cp_commit();

    const uint32_t aSwz = (uint32_t)(lane & 7) << 4;
    const uint32_t kbBase = (uint32_t)(lane >> 4) << 4;
    uint32_t rowA[4], rowB[2];
    #pragma unroll
    for (int mt = 0; mt < 4; ++mt)
        rowA[mt] = (uint32_t)(warpM * 64 + mt * 16 + (lane & 15)) * 128;
    #pragma unroll
    for (int c = 0; c < 2; ++c)
        rowB[c] = (uint32_t)(warpN * 32 + c * 16 + (lane & 15)) * 128;

    for (int it = 0; it < NITER; ++it) {
        int buf = it & 1;
        if (it + 1 < NITER) { load_tiles(it + 1, buf ^ 1); cp_commit(); CP_WAIT1(); }
        else                { CP_WAIT0(); }
        __syncthreads();
        const uint32_t sAh = smem0 + buf * BUFB;
        const uint32_t sAl = sAh + ASZ;
        const uint32_t sBh = sAl + ASZ;
        const uint32_t sBl = sBh + BSZ;
        #pragma unroll
        for (int ks = 0; ks < 4; ++ks) {
            const uint32_t kb = ((uint32_t)(ks * 32) + kbBase) ^ aSwz;
            uint32_t ah[4][4], al[4][4];
            #pragma unroll
            for (int mt = 0; mt < 4; ++mt) {
                LDM4(ah[mt], sAh + rowA[mt] + kb);
                LDM4(al[mt], sAl + rowA[mt] + kb);
            }
            #pragma unroll
            for (int c = 0; c < 2; ++c) {
                uint32_t bh[4], bl[4];
                LDM4(bh, sBh + rowB[c] + kb);
                LDM4(bl, sBl + rowB[c] + kb);
                #pragma unroll
                for (int mt = 0; mt < 4; ++mt) {
                    MMA3(acc[mt][2 * c], acc[mt][2 * c + 1], ah[mt], al[mt], bh, bl);
                }
            }
        }
        if (it + 1 < NITER) __syncthreads();
    }

    const int tr = lane >> 2, tc = (lane & 3) * 2;
    #pragma unroll
    for (int mt = 0; mt < 4; ++mt)
        #pragma unroll
        for (int half = 0; half < 2; ++half) {
            int m = m0 + warpM * 64 + mt * 16 + tr + half * 8;
            #pragma unroll
            for (int nt = 0; nt < 4; ++nt) {
                int n = n0 + warpN * 32 + nt * 8 + tc;
                float v0 = fmaxf(acc[mt][nt][half * 2 + 0] + bias[n], 0.f);
                float v1 = fmaxf(acc[mt][nt][half * 2 + 1] + bias[n + 1], 0.f);
                *reinterpret_cast<float2*>(Of32 + (size_t)m * 1024 + n) =
                    make_float2(v0, v1);
            }
        }
}

// ---------------------------------------------------------------------------
// Weight prep (identical to validated R8 versions)
// ---------------------------------------------------------------------------
#define PREP_SA   4096
#define PREP_C1   (128 * 192)
#define PREP_C2   (256 * 384)
#define PREP_C3   (256 * 768)
#define PREP_WPT  4096
#define PREP_WB1  4096
#define PREP_WB2  8192
#define PREP_WB3  32768
#define PREP_SMALL (PREP_SA + PREP_C1 + PREP_C2 + PREP_C3 + PREP_WPT + \
                    PREP_WB1 + PREP_WB2 + PREP_WB3)

__global__ void prep_small_kernel(
    const float* __restrict__ Wp, const float* __restrict__ W1,
    const float* __restrict__ W2, const float* __restrict__ W3,
    const float* __restrict__ Wb1, const float* __restrict__ Wb2,
    const float* __restrict__ Wb3,
    bf16* wah, bf16* wal, bf16* w1h, bf16* w1l, bf16* w2h, bf16* w2l,
    bf16* w3h, bf16* w3l,
    float* wpt, float* wb1t, float* wb2t, float* wb3t)
{
    int idx = blockIdx.x * 256 + threadIdx.x;
    if (idx >= PREP_SMALL) return;
    bf16 h, l;
    if (idx < PREP_SA) {
        int p = idx >> 6, i = idx & 63;
        split2(Wp[p * 128 + i * 2 + 1], h, l);
        wah[idx] = h; wal[idx] = l;
        return;
    }
    idx -= PREP_SA;
    if (idx < PREP_C1) {
        int o = idx / 192, rem = idx - o * 192;
        int i = rem / 3, j = rem - i * 3;
        split2(W1[idx], h, l);
        w1h[o * 192 + j * 64 + i] = h; w1l[o * 192 + j * 64 + i] = l;
        return;
    }
    idx -= PREP_C1;
    if (idx < PREP_C2) {
        int o = idx / 384, rem = idx - o * 384;
        int i = rem / 3, j = rem - i * 3;
        split2(W2[idx], h, l);
        w2h[o * 384 + j * 128 + i] = h; w2l[o * 384 + j * 128 + i] = l;
        return;
    }
    idx -= PREP_C2;
    if (idx < PREP_C3) {
        int o = idx / 768, rem = idx - o * 768;
        int i = rem / 3, j = rem - i * 3;
        split2(W3[idx], h, l);
        w3h[o * 768 + j * 256 + i] = h; w3l[o * 768 + j * 256 + i] = l;
        return;
    }
    idx -= PREP_C3;
    if (idx < PREP_WPT) { int i = idx >> 6, p = idx & 63; wpt[idx] = Wp[p * 128 + i * 2]; return; }
    idx -= PREP_WPT;
    if (idx < PREP_WB1) { int i = idx >> 6, n = idx & 63; wb1t[idx] = Wb1[n * 64 + i]; return; }
    idx -= PREP_WB1;
    if (idx < PREP_WB2) { int i = idx >> 7, n = idx & 127; wb2t[idx] = Wb2[n * 64 + i]; return; }
    idx -= PREP_WB2;
    { int i = idx >> 8, n = idx & 255; wb3t[idx] = Wb3[n * 128 + i]; }
}

__global__ void __launch_bounds__(256) prep_fc_kernel(
    const float* __restrict__ Wfc1, bf16* __restrict__ wfh,
    bf16* __restrict__ wfl)
{
    extern __shared__ float s[];
    const int n = blockIdx.x, tid = threadIdx.x;
    const float* src = Wfc1 + (size_t)n * 16640;
    for (int k = tid; k < 16384; k += 256) {
        int c = k >> 6, p = k & 63;
        s[c * 65 + p] = src[k];
    }
    __syncthreads();
    bf16* dh = wfh + (size_t)n * 16640;
    bf16* dl = wfl + (size_t)n * 16640;
    for (int k2 = tid; k2 < 16384; k2 += 256) {
        int p = k2 >> 8, c = k2 & 255;
        bf16 h, l;
        split2(s[c * 65 + p], h, l);
        dh[k2] = h; dl[k2] = l;
    }
    for (int k2 = 16384 + tid; k2 < 16640; k2 += 256) {
        bf16 h, l;
        split2(src[k2], h, l);
        dh[k2] = h; dl[k2] = l;
    }
}

#define BB 16
__global__ void __launch_bounds__(256) branch_s0_kernel(
    const float* __restrict__ x,
    const float* __restrict__ wpt,  const float* __restrict__ bp,
    const float* __restrict__ wb1t, const float* __restrict__ bb1,
    const float* __restrict__ wb2t, const float* __restrict__ bb2,
    const float* __restrict__ wb3t, const float* __restrict__ bb3,
    float* __restrict__ s0, bf16* __restrict__ zh, bf16* __restrict__ zl)
{
    __shared__ float x0s[BB][64], f1s[BB][64], f2s[BB][128];
    const int tid = threadIdx.x;
    const int b0 = blockIdx.x * BB;
    #pragma unroll
    for (int t = 0; t < 4; ++t) {
        int idx = tid + t * 256;
        int bs = idx >> 6, i = idx & 63;
        x0s[bs][i] = x[(size_t)(b0 + bs) * 16384 + i];
    }
    __syncthreads();
    #pragma unroll
    for (int t = 0; t < 4; ++t) {
        int idx = tid + t * 256;
        int bs = idx >> 6, n = idx & 63;
        float a0 = bp[n], a1 = bb1[n];
        #pragma unroll 8
        for (int i = 0; i < 64; ++i) {
            float xv = x0s[bs][i];
            a0 += wpt[i * 64 + n] * xv;
            a1 += wb1t[i * 64 + n] * xv;
        }
        s0[(size_t)(b0 + bs) * 64 + n] = a0;
        f1s[bs][n] = fmaxf(a1, 0.f);
    }
    __syncthreads();
    #pragma unroll
    for (int t = 0; t < 8; ++t) {
        int idx = tid + t * 256;
        int bs = idx >> 7, n = idx & 127;
        float a = bb2[n];
        #pragma unroll 8
        for (int i = 0; i < 64; ++i) a += wb2t[i * 128 + n] * f1s[bs][i];
        f2s[bs][n] = fmaxf(a, 0.f);
    }
    __syncthreads();
    #pragma unroll
    for (int t = 0; t < 16; ++t) {
        int idx = tid + t * 256;
        int bs = idx >> 8, n = idx & 255;
        float a = bb3[n];
        #pragma unroll 8
        for (int i = 0; i < 128; ++i) a += wb3t[i * 256 + n] * f2s[bs][i];
        float v = fmaxf(a, 0.f);
        bf16 h, l;
        split2(v, h, l);
        size_t o = (size_t)(b0 + bs) * 16640 + 16384 + n;
        zh[o] = h; zl[o] = l;
    }
}

__global__ void __launch_bounds__(128) fc2_kernel(
    const float* __restrict__ f1, const float* __restrict__ W,
    const float* __restrict__ bias, float* __restrict__ out)
{
    __shared__ float red0[4], red1[4];
    const int b = blockIdx.x, tid = threadIdx.x;
    const float* hb = f1 + (size_t)b * 1024;
    float s0 = 0.f, s1 = 0.f;
    for (int k = tid; k < 1024; k += 128) {
        float v = hb[k];
        s0 += v * W[k];
        s1 += v * W[1024 + k];
    }
    #pragma unroll
    for (int off = 16; off > 0; off >>= 1) {
        s0 += __shfl_down_sync(0xffffffffu, s0, off);
        s1 += __shfl_down_sync(0xffffffffu, s1, off);
    }
    if ((tid & 31) == 0) { red0[tid >> 5] = s0; red1[tid >> 5] = s1; }
    __syncthreads();
    if (tid == 0) {
        out[b * 2 + 0] = red0[0] + red0[1] + red0[2] + red0[3] + bias[0];
        out[b * 2 + 1] = red1[0] + red1[1] + red1[2] + red1[3] + bias[1];
    }
}

// ---------------------------------------------------------------------------
// Launch
// ---------------------------------------------------------------------------
extern "C" void kernel_launch(void* const* d_in, const int* in_sizes, int n_in,
                              void* d_out, int out_size)
{
    const float* x    = (const float*)d_in[0];
    const float* Wp   = (const float*)d_in[1];
    const float* bp   = (const float*)d_in[2];
    const float* W1   = (const float*)d_in[3];
    const float* b1   = (const float*)d_in[4];
    const float* W2   = (const float*)d_in[5];
    const float* b2   = (const float*)d_in[6];
    const float* W3   = (const float*)d_in[7];
    const float* b3   = (const float*)d_in[8];
    const float* Wb1  = (const float*)d_in[9];
    const float* bb1  = (const float*)d_in[10];
    const float* Wb2  = (const float*)d_in[11];
    const float* bb2  = (const float*)d_in[12];
    const float* Wb3  = (const float*)d_in[13];
    const float* bb3  = (const float*)d_in[14];
    const float* Wfc1 = (const float*)d_in[15];
    const float* bfc1 = (const float*)d_in[16];
    const float* Wfc2 = (const float*)d_in[17];
    const float* bfc2 = (const float*)d_in[18];
    float* out = (float*)d_out;

    static void *zh, *zl, *f1, *s0;
    static void *wah, *wal, *w1h, *w1l, *w2h, *w2l, *w3h, *w3l, *wfh, *wfl;
    static void *wpt, *wb1t, *wb2t, *wb3t;
    static bool init = false;
    if (!init) {
        cudaGetSymbolAddress(&zh,  g_zh);  cudaGetSymbolAddress(&zl,  g_zl);
        cudaGetSymbolAddress(&f1,  g_f1);  cudaGetSymbolAddress(&s0,  g_s0);
        cudaGetSymbolAddress(&wah, g_wah); cudaGetSymbolAddress(&wal, g_wal);
        cudaGetSymbolAddress(&w1h, g_w1h); cudaGetSymbolAddress(&w1l, g_w1l);
        cudaGetSymbolAddress(&w2h, g_w2h); cudaGetSymbolAddress(&w2l, g_w2l);
        cudaGetSymbolAddress(&w3h, g_w3h); cudaGetSymbolAddress(&w3l, g_w3l);
        cudaGetSymbolAddress(&wfh, g_wfh); cudaGetSymbolAddress(&wfl, g_wfl);
        cudaGetSymbolAddress(&wpt, g_wpt); cudaGetSymbolAddress(&wb1t, g_wb1t);
        cudaGetSymbolAddress(&wb2t, g_wb2t); cudaGetSymbolAddress(&wb3t, g_wb3t);
        cudaFuncSetAttribute(fused_conv_kernel,
                             cudaFuncAttributeMaxDynamicSharedMemorySize, FUSED_SMEM);
        cudaFuncSetAttribute(fc1_kernel,
                             cudaFuncAttributeMaxDynamicSharedMemorySize, 131072);
        cudaFuncSetAttribute(prep_fc_kernel,
                             cudaFuncAttributeMaxDynamicSharedMemorySize, 256 * 65 * 4);
        init = true;
    }

    prep_small_kernel<<<(PREP_SMALL + 255) / 256, 256>>>(
        Wp, W1, W2, W3, Wb1, Wb2, Wb3,
        (bf16*)wah, (bf16*)wal, (bf16*)w1h, (bf16*)w1l, (bf16*)w2h, (bf16*)w2l,
        (bf16*)w3h, (bf16*)w3l,
        (float*)wpt, (float*)wb1t, (float*)wb2t, (float*)wb3t);
    prep_fc_kernel<<<1024, 256, 256 * 65 * 4>>>(Wfc1, (bf16*)wfh, (bf16*)wfl);

    branch_s0_kernel<<<2048 / BB, 256>>>(
        x, (const float*)wpt, bp, (const float*)wb1t, bb1,
        (const float*)wb2t, bb2, (const float*)wb3t, bb3,
        (float*)s0, (bf16*)zh, (bf16*)zl);

    fused_conv_kernel<<<2048, 256, FUSED_SMEM>>>(
        x, (const float*)s0,
        (const bf16*)wah, (const bf16*)wal, (const bf16*)w1h, (const bf16*)w1l,
        (const bf16*)w2h, (const bf16*)w2l, (const bf16*)w3h, (const bf16*)w3l,
        b1, b2, b3, (bf16*)zh, (bf16*)zl);

    fc1_kernel<<<dim3(8, 16), 256, 131072>>>(
        (const bf16*)zh, (const bf16*)zl, (const bf16*)wfh, (const bf16*)wfl,
        bfc1, (float*)f1);

    fc2_kernel<<<2048, 128>>>((const float*)f1, Wfc2, bfc2, out);
}

// round 11
// speedup vs baseline: 1.0118x; 1.0118x over previous
#include <cuda_runtime.h>
#include <cuda_bf16.h>
#include <cstdint>

typedef __nv_bfloat16 bf16;

// ---------------------------------------------------------------------------
// Static scratch
// ---------------------------------------------------------------------------
__device__ __align__(1024) bf16 g_zh [(size_t)2048 * 16640];
__device__ __align__(1024) bf16 g_zl [(size_t)2048 * 16640];
__device__ __align__(1024) float g_f1[(size_t)2048 * 1024];
__device__ __align__(1024) float g_s0[2048 * 64];
__device__ __align__(1024) bf16 g_wah[64 * 64],   g_wal[64 * 64];
__device__ __align__(1024) bf16 g_w1h[128 * 192], g_w1l[128 * 192];
__device__ __align__(1024) bf16 g_w2h[256 * 384], g_w2l[256 * 384];
__device__ __align__(1024) bf16 g_w3h[256 * 768], g_w3l[256 * 768];
__device__ __align__(1024) bf16 g_wfh[(size_t)1024 * 16640];
__device__ __align__(1024) bf16 g_wfl[(size_t)1024 * 16640];
__device__ __align__(1024) float g_wpt [64 * 64];
__device__ __align__(1024) float g_wb1t[64 * 64];
__device__ __align__(1024) float g_wb2t[64 * 128];
__device__ __align__(1024) float g_wb3t[128 * 256];

// ---------------------------------------------------------------------------
// Helpers
// ---------------------------------------------------------------------------
__device__ __forceinline__ uint32_t cvta_smem(const void* p) {
    return (uint32_t)__cvta_generic_to_shared(p);
}
__device__ __forceinline__ void cpa16(uint32_t dst, const void* src, int sz) {
    asm volatile("cp.async.cg.shared.global [%0], [%1], 16, %2;"
                 :: "r"(dst), "l"(src), "r"(sz) : "memory");
}
__device__ __forceinline__ void cp_commit() {
    asm volatile("cp.async.commit_group;" ::: "memory");
}
#define CP_WAIT1() asm volatile("cp.async.wait_group 1;" ::: "memory")
#define CP_WAIT0() asm volatile("cp.async.wait_group 0;" ::: "memory")
#define LDM4(r, addr)                                                         \
    asm volatile("ldmatrix.sync.aligned.m8n8.x4.shared.b16 "                  \
                 "{%0,%1,%2,%3}, [%4];"                                       \
                 : "=r"((r)[0]), "=r"((r)[1]), "=r"((r)[2]), "=r"((r)[3])     \
                 : "r"(addr))

__device__ __forceinline__ void mma16816(float* d, const uint32_t* a,
                                         uint32_t b0, uint32_t b1) {
    asm volatile(
        "mma.sync.aligned.m16n8k16.row.col.f32.bf16.bf16.f32 "
        "{%0,%1,%2,%3}, {%4,%5,%6,%7}, {%8,%9}, {%0,%1,%2,%3};"
        : "+f"(d[0]), "+f"(d[1]), "+f"(d[2]), "+f"(d[3])
        : "r"(a[0]), "r"(a[1]), "r"(a[2]), "r"(a[3]), "r"(b0), "r"(b1));
}
__device__ __forceinline__ void split2(float v, bf16& h, bf16& l) {
    h = __float2bfloat16(v);
    l = __float2bfloat16(v - __bfloat162float(h));
}
__device__ __forceinline__ uint32_t pack2(bf16 a, bf16 b) {
    return (uint32_t)__bfloat16_as_ushort(a) |
           ((uint32_t)__bfloat16_as_ushort(b) << 16);
}
#define MMA3(acc0, acc1, AH, AL, BH, BL)                                      \
    mma16816(acc0, AH, BH[0], BH[2]); mma16816(acc1, AH, BH[1], BH[3]);       \
    mma16816(acc0, AH, BL[0], BL[2]); mma16816(acc1, AH, BL[1], BL[3]);       \
    mma16816(acc0, AL, BH[0], BH[2]); mma16816(acc1, AL, BH[1], BH[3]);

// ---------------------------------------------------------------------------
// Fused per-batch conv chain (512 threads, 16 warps, acc<=64 regs/stage)
// SMEM regions identical to previous round.
// ---------------------------------------------------------------------------
#define P0 0u
#define P1 81920u
#define XA_H (P1 + 0u)
#define XA_L (P1 + 36864u)
#define WA_H (P1 + 73728u)
#define WA_L (P1 + 82944u)
#define C1B(t) (P1 + 73728u + (uint32_t)(t) * 20480u)
#define H0_H (P0 + 0u)
#define H0_L (P0 + 37152u)
#define C23B(t) (P0 + (uint32_t)(t) * 40960u)
#define H1_H (P1 + 0u)
#define H1_L (P1 + 69904u)
#define H1_ODD 35088u
#define H2_H (P1 + 0u)
#define H2_L (P1 + 68640u)
#define H2_ODD 34320u
#define FUSED_SMEM 221728

__global__ void __launch_bounds__(512, 1) fused_conv_kernel(
    const float* __restrict__ x, const float* __restrict__ s0g,
    const bf16* __restrict__ wah, const bf16* __restrict__ wal,
    const bf16* __restrict__ w1h, const bf16* __restrict__ w1l,
    const bf16* __restrict__ w2h, const bf16* __restrict__ w2l,
    const bf16* __restrict__ w3h, const bf16* __restrict__ w3l,
    const float* __restrict__ b1, const float* __restrict__ b2,
    const float* __restrict__ b3,
    bf16* __restrict__ zh, bf16* __restrict__ zl)
{
    extern __shared__ __align__(1024) char smem_c[];
    const uint32_t S = cvta_smem(smem_c);
    const int tid = threadIdx.x;
    const int lane = tid & 31;
    const int wid = tid >> 5;                  // 0..15
    const int b = blockIdx.x;
    const int laneM = lane & 15;
    const uint32_t laneK = (uint32_t)(lane >> 4) << 4;
    const int tr = lane >> 2;
    const int tc = (lane & 3) * 2;
    const float* xb = x + (size_t)b * 16384;

    // ===== load xA (split) + wa =========================================
    #pragma unroll
    for (int t = 0; t < 8; ++t) {
        int idx = tid + t * 512;
        int row = idx >> 4, q = idx & 15;
        uint32_t off = (uint32_t)row * 144 + (uint32_t)q * 8;
        if (row < 255) {
            float4 v = *reinterpret_cast<const float4*>(xb + (row + 1) * 64 + q * 4);
            bf16 h0, h1, h2, h3, l0, l1, l2, l3;
            split2(v.x, h0, l0); split2(v.y, h1, l1);
            split2(v.z, h2, l2); split2(v.w, h3, l3);
            *reinterpret_cast<uint2*>(smem_c + XA_H + off) =
                make_uint2(pack2(h0, h1), pack2(h2, h3));
            *reinterpret_cast<uint2*>(smem_c + XA_L + off) =
                make_uint2(pack2(l0, l1), pack2(l2, l3));
        } else {
            *reinterpret_cast<uint2*>(smem_c + XA_H + off) = make_uint2(0u, 0u);
            *reinterpret_cast<uint2*>(smem_c + XA_L + off) = make_uint2(0u, 0u);
        }
    }
    #pragma unroll
    for (int t = 0; t < 2; ++t) {
        int idx = tid + t * 512;
        int plane = idx >> 9, v = idx & 511;
        int n = v >> 3, q = v & 7;
        const bf16* src = (plane ? wal : wah) + n * 64 + q * 8;
        cpa16(S + (plane ? WA_L : WA_H) + (uint32_t)n * 144 + (uint32_t)q * 16,
              src, 16);
    }
    cp_commit(); CP_WAIT0();
    __syncthreads();

    // ===== Stage A: M=256(255) N=64 K=64; warps 4M x 4N =================
    {
        const int m0w = (wid >> 2) * 64;
        const int n0w = (wid & 3) * 16;
        float acc[4][2][4] = {};
        #pragma unroll
        for (int ks = 0; ks < 4; ++ks) {
            uint32_t ah[4][4], al[4][4];
            #pragma unroll
            for (int mt = 0; mt < 4; ++mt) {
                uint32_t ra = (uint32_t)(m0w + mt * 16 + laneM) * 144 +
                              (uint32_t)ks * 32 + laneK;
                LDM4(ah[mt], S + XA_H + ra);
                LDM4(al[mt], S + XA_L + ra);
            }
            uint32_t rb = (uint32_t)(n0w + laneM) * 144 +
                          (uint32_t)ks * 32 + laneK;
            uint32_t bh[4], bl[4];
            LDM4(bh, S + WA_H + rb);
            LDM4(bl, S + WA_L + rb);
            #pragma unroll
            for (int mt = 0; mt < 4; ++mt) {
                MMA3(acc[mt][0], acc[mt][1], ah[mt], al[mt], bh, bl);
            }
        }
        __syncthreads();
        #pragma unroll
        for (int mt = 0; mt < 4; ++mt)
            #pragma unroll
            for (int half = 0; half < 2; ++half) {
                int m = m0w + mt * 16 + tr + half * 8;
                if (m < 255) {
                    #pragma unroll
                    for (int nt = 0; nt < 2; ++nt) {
                        int n = n0w + nt * 8 + tc;
                        float v0 = fmaxf(acc[mt][nt][half * 2 + 0] + s0g[b * 64 + n], 0.f);
                        float v1 = fmaxf(acc[mt][nt][half * 2 + 1] + s0g[b * 64 + n + 1], 0.f);
                        bf16 h0v, h1v, l0v, l1v;
                        split2(v0, h0v, l0v); split2(v1, h1v, l1v);
                        uint32_t off = (uint32_t)(m + 1) * 144 + (uint32_t)n * 2;
                        *reinterpret_cast<uint32_t*>(smem_c + H0_H + off) = pack2(h0v, h1v);
                        *reinterpret_cast<uint32_t*>(smem_c + H0_L + off) = pack2(l0v, l1v);
                    }
                }
            }
        if (tid < 96) {   // zero h0 halo rows 0, 256, 257
            int rs = tid >> 5, q = tid & 31;
            uint32_t rr = (rs == 0) ? 0u : (rs == 1 ? 256u : 257u);
            uint32_t off = rr * 144 + (uint32_t)q * 4;
            *reinterpret_cast<uint32_t*>(smem_c + H0_H + off) = 0u;
            *reinterpret_cast<uint32_t*>(smem_c + H0_L + off) = 0u;
        }
        __syncthreads();
    }

    // ===== Conv1: M=256(255) N=128 K=192; warps 4M x 4N =================
    {
        const int m0w = (wid >> 2) * 64;
        const int n0w = (wid & 3) * 32;
        float acc[4][4][4] = {};
        auto loadB = [&](int t, int buf) {
            int j = t >> 1, c32 = t & 1;
            #pragma unroll
            for (int r4 = 0; r4 < 2; ++r4) {
                int idx = tid + r4 * 512;
                int plane = idx >> 9, v = idx & 511;
                int n = v >> 2, q = v & 3;
                const bf16* src = (plane ? w1l : w1h) + n * 192 + j * 64 + c32 * 32 + q * 8;
                cpa16(S + C1B(buf) + (uint32_t)plane * 10240u +
                      (uint32_t)n * 80 + (uint32_t)q * 16, src, 16);
            }
        };
        loadB(0, 0); cp_commit();
        #pragma unroll 1
        for (int t = 0; t < 6; ++t) {
            if (t < 5) { loadB(t + 1, (t + 1) & 1); cp_commit(); CP_WAIT1(); }
            else       { CP_WAIT0(); }
            __syncthreads();
            const int j = t >> 1, c32 = t & 1;
            const uint32_t bB = C1B(t & 1);
            #pragma unroll
            for (int ks = 0; ks < 2; ++ks) {
                uint32_t ah[4][4], al[4][4];
                #pragma unroll
                for (int mt = 0; mt < 4; ++mt) {
                    uint32_t ra = (uint32_t)(m0w + mt * 16 + laneM + j) * 144 +
                                  (uint32_t)(c32 * 64 + ks * 32) + laneK;
                    LDM4(ah[mt], S + H0_H + ra);
                    LDM4(al[mt], S + H0_L + ra);
                }
                #pragma unroll
                for (int c = 0; c < 2; ++c) {
                    uint32_t rb = (uint32_t)(n0w + c * 16 + laneM) * 80 +
                                  (uint32_t)ks * 32 + laneK;
                    uint32_t bh[4], bl[4];
                    LDM4(bh, S + bB + rb);
                    LDM4(bl, S + bB + 10240u + rb);
                    #pragma unroll
                    for (int mt = 0; mt < 4; ++mt) {
                        MMA3(acc[mt][2 * c], acc[mt][2 * c + 1], ah[mt], al[mt], bh, bl);
                    }
                }
            }
            __syncthreads();
        }
        #pragma unroll
        for (int mt = 0; mt < 4; ++mt)
            #pragma unroll
            for (int half = 0; half < 2; ++half) {
                int m = m0w + mt * 16 + tr + half * 8;
                if (m < 255) {
                    uint32_t rr = (uint32_t)(m + 1);
                    uint32_t base = ((rr & 1) ? H1_ODD : 0u) + (rr >> 1) * 272;
                    #pragma unroll
                    for (int nt = 0; nt < 4; ++nt) {
                        int n = n0w + nt * 8 + tc;
                        float v0 = fmaxf(acc[mt][nt][half * 2 + 0] + b1[n], 0.f);
                        float v1 = fmaxf(acc[mt][nt][half * 2 + 1] + b1[n + 1], 0.f);
                        bf16 h0v, h1v, l0v, l1v;
                        split2(v0, h0v, l0v); split2(v1, h1v, l1v);
                        uint32_t off = base + (uint32_t)n * 2;
                        *reinterpret_cast<uint32_t*>(smem_c + H1_H + off) = pack2(h0v, h1v);
                        *reinterpret_cast<uint32_t*>(smem_c + H1_L + off) = pack2(l0v, l1v);
                    }
                }
            }
        if (tid < 128) {  // zero h1 halo rows 0, 256
            int rs = tid >> 6, q = tid & 63;
            uint32_t rr = rs ? 256u : 0u;
            uint32_t off = ((rr & 1) ? H1_ODD : 0u) + (rr >> 1) * 272 + (uint32_t)q * 4;
            *reinterpret_cast<uint32_t*>(smem_c + H1_H + off) = 0u;
            *reinterpret_cast<uint32_t*>(smem_c + H1_L + off) = 0u;
        }
        __syncthreads();
    }

    // ===== Conv2: M=128 N=256 K=384 stride2; warps 4M x 4N ==============
    {
        const int m0w = (wid >> 2) * 32;
        const int n0w = (wid & 3) * 64;
        float acc[2][8][4] = {};
        auto loadB = [&](int t, int buf) {
            int j = t >> 2, c32 = t & 3;
            #pragma unroll
            for (int r4 = 0; r4 < 4; ++r4) {
                int idx = tid + r4 * 512;
                int plane = idx >> 10, v = idx & 1023;
                int n = v >> 2, q = v & 3;
                const bf16* src = (plane ? w2l : w2h) + n * 384 + j * 128 + c32 * 32 + q * 8;
                cpa16(S + C23B(buf) + (uint32_t)plane * 20480u +
                      (uint32_t)n * 80 + (uint32_t)q * 16, src, 16);
            }
        };
        loadB(0, 0); cp_commit();
        #pragma unroll 1
        for (int t = 0; t < 12; ++t) {
            if (t < 11) { loadB(t + 1, (t + 1) & 1); cp_commit(); CP_WAIT1(); }
            else        { CP_WAIT0(); }
            __syncthreads();
            const int j = t >> 2, c32 = t & 3;
            const uint32_t bB = C23B(t & 1);
            const uint32_t sel = (uint32_t)(j & 1) * H1_ODD;
            const int jdiv = j >> 1;
            #pragma unroll
            for (int ks = 0; ks < 2; ++ks) {
                uint32_t ah[2][4], al[2][4];
                #pragma unroll
                for (int mt = 0; mt < 2; ++mt) {
                    uint32_t ra = sel + (uint32_t)(m0w + mt * 16 + laneM + jdiv) * 272 +
                                  (uint32_t)(c32 * 64 + ks * 32) + laneK;
                    LDM4(ah[mt], S + H1_H + ra);
                    LDM4(al[mt], S + H1_L + ra);
                }
                #pragma unroll
                for (int c = 0; c < 4; ++c) {
                    uint32_t rb = (uint32_t)(n0w + c * 16 + laneM) * 80 +
                                  (uint32_t)ks * 32 + laneK;
                    uint32_t bh[4], bl[4];
                    LDM4(bh, S + bB + rb);
                    LDM4(bl, S + bB + 20480u + rb);
                    #pragma unroll
                    for (int mt = 0; mt < 2; ++mt) {
                        MMA3(acc[mt][2 * c], acc[mt][2 * c + 1], ah[mt], al[mt], bh, bl);
                    }
                }
            }
            __syncthreads();
        }
        #pragma unroll
        for (int mt = 0; mt < 2; ++mt)
            #pragma unroll
            for (int half = 0; half < 2; ++half) {
                int m = m0w + mt * 16 + tr + half * 8;
                uint32_t rr = (uint32_t)(m + 1);
                uint32_t base = ((rr & 1) ? H2_ODD : 0u) + (rr >> 1) * 528;
                #pragma unroll
                for (int nt = 0; nt < 8; ++nt) {
                    int n = n0w + nt * 8 + tc;
                    float v0 = fmaxf(acc[mt][nt][half * 2 + 0] + b2[n], 0.f);
                    float v1 = fmaxf(acc[mt][nt][half * 2 + 1] + b2[n + 1], 0.f);
                    bf16 h0v, h1v, l0v, l1v;
                    split2(v0, h0v, l0v); split2(v1, h1v, l1v);
                    uint32_t off = base + (uint32_t)n * 2;
                    *reinterpret_cast<uint32_t*>(smem_c + H2_H + off) = pack2(h0v, h1v);
                    *reinterpret_cast<uint32_t*>(smem_c + H2_L + off) = pack2(l0v, l1v);
                }
            }
        if (tid < 256) {  // zero h2 halo rows 0, 129
            int rs = tid >> 7, q = tid & 127;
            uint32_t rr = rs ? 129u : 0u;
            uint32_t off = ((rr & 1) ? H2_ODD : 0u) + (rr >> 1) * 528 + (uint32_t)q * 4;
            *reinterpret_cast<uint32_t*>(smem_c + H2_H + off) = 0u;
            *reinterpret_cast<uint32_t*>(smem_c + H2_L + off) = 0u;
        }
        __syncthreads();
    }

    // ===== Conv3: M=64 N=256 K=768 stride2; warps 2M x 8N ===============
    {
        const int m0w = (wid >> 3) * 32;
        const int n0w = (wid & 7) * 32;
        float acc[2][4][4] = {};
        auto loadB = [&](int t, int buf) {
            int j = t >> 3, c32 = t & 7;
            #pragma unroll
            for (int r4 = 0; r4 < 4; ++r4) {
                int idx = tid + r4 * 512;
                int plane = idx >> 10, v = idx & 1023;
                int n = v >> 2, q = v & 3;
                const bf16* src = (plane ? w3l : w3h) + n * 768 + j * 256 + c32 * 32 + q * 8;
                cpa16(S + C23B(buf) + (uint32_t)plane * 20480u +
                      (uint32_t)n * 80 + (uint32_t)q * 16, src, 16);
            }
        };
        loadB(0, 0); cp_commit();
        #pragma unroll 1
        for (int t = 0; t < 24; ++t) {
            if (t < 23) { loadB(t + 1, (t + 1) & 1); cp_commit(); CP_WAIT1(); }
            else        { CP_WAIT0(); }
            __syncthreads();
            const int j = t >> 3, c32 = t & 7;
            const uint32_t bB = C23B(t & 1);
            const uint32_t sel = (uint32_t)(j & 1) * H2_ODD;
            const int jdiv = j >> 1;
            #pragma unroll
            for (int ks = 0; ks < 2; ++ks) {
                uint32_t ah[2][4], al[2][4];
                #pragma unroll
                for (int mt = 0; mt < 2; ++mt) {
                    uint32_t ra = sel + (uint32_t)(m0w + mt * 16 + laneM + jdiv) * 528 +
                                  (uint32_t)(c32 * 64 + ks * 32) + laneK;
                    LDM4(ah[mt], S + H2_H + ra);
                    LDM4(al[mt], S + H2_L + ra);
                }
                #pragma unroll
                for (int c = 0; c < 2; ++c) {
                    uint32_t rb = (uint32_t)(n0w + c * 16 + laneM) * 80 +
                                  (uint32_t)ks * 32 + laneK;
                    uint32_t bh[4], bl[4];
                    LDM4(bh, S + bB + rb);
                    LDM4(bl, S + bB + 20480u + rb);
                    #pragma unroll
                    for (int mt = 0; mt < 2; ++mt) {
                        MMA3(acc[mt][2 * c], acc[mt][2 * c + 1], ah[mt], al[mt], bh, bl);
                    }
                }
            }
            __syncthreads();
        }
        bf16* zhb = zh + (size_t)b * 16640;
        bf16* zlb = zl + (size_t)b * 16640;
        #pragma unroll
        for (int mt = 0; mt < 2; ++mt)
            #pragma unroll
            for (int half = 0; half < 2; ++half) {
                int m = m0w + mt * 16 + tr + half * 8;
                #pragma unroll
                for (int nt = 0; nt < 4; ++nt) {
                    int n = n0w + nt * 8 + tc;
                    float v0 = fmaxf(acc[mt][nt][half * 2 + 0] + b3[n], 0.f);
                    float v1 = fmaxf(acc[mt][nt][half * 2 + 1] + b3[n + 1], 0.f);
                    bf16 h0v, h1v, l0v, l1v;
                    split2(v0, h0v, l0v); split2(v1, h1v, l1v);
                    *reinterpret_cast<uint32_t*>(zhb + m * 256 + n) = pack2(h0v, h1v);
                    *reinterpret_cast<uint32_t*>(zlb + m * 256 + n) = pack2(l0v, l1v);
                }
            }
    }
}

// ---------------------------------------------------------------------------
// fc1: 128x128 tiles, BK=64, warps 2M x 4N (validated template)
// ---------------------------------------------------------------------------
__global__ void __launch_bounds__(256, 1)
fc1_kernel(const bf16* __restrict__ Ahi, const bf16* __restrict__ Alo,
           const bf16* __restrict__ Whi, const bf16* __restrict__ Wlo,
           const float* __restrict__ bias, float* __restrict__ Of32)
{
    constexpr int KTOT = 16640, NITER = 260;
    constexpr int ASZ = 128 * 128, BSZ = 128 * 128, BUFB = 2 * ASZ + 2 * BSZ;
    extern __shared__ __align__(1024) char smem_c[];
    const uint32_t smem0 = cvta_smem(smem_c);
    const int tid = threadIdx.x;
    const int lane = tid & 31;
    const int wid = tid >> 5;
    const int warpM = wid >> 2, warpN = wid & 3;
    const int n0 = blockIdx.x * 128, m0 = blockIdx.y * 128;

    float acc[4][4][4] = {};
    auto load_tiles = [&](int it, int buf) {
        const int k0 = it * 64;
        const uint32_t sb = smem0 + buf * BUFB;
        #pragma unroll
        for (int rep = 0; rep < 4; ++rep) {
            int v = tid + rep * 256;
            int row = v >> 3, q = v & 7;
            size_t off = (size_t)(m0 + row) * KTOT + k0 + q * 8;
            uint32_t so = row * 128 + ((q * 16) ^ ((row & 7) << 4));
            cpa16(sb + so, Ahi + off, 16);
            cpa16(sb + ASZ + so, Alo + off, 16);
        }
        #pragma unroll
        for (int rep = 0; rep < 4; ++rep) {
            int v = tid + rep * 256;
            int n = v >> 3, q = v & 7;
            size_t off = (size_t)(n0 + n) * KTOT + k0 + q * 8;
            uint32_t so = n * 128 + ((q * 16) ^ ((n & 7) << 4));
            cpa16(sb + 2 * ASZ + so, Whi + off, 16);
            cpa16(sb + 2 * ASZ + BSZ + so, Wlo + off, 16);
        }
    };
    load_tiles(0, 0); cp_commit();

    const uint32_t aSwz = (uint32_t)(lane & 7) << 4;
    const uint32_t kbBase = (uint32_t)(lane >> 4) << 4;
    uint32_t rowA[4], rowB[2];
    #pragma unroll
    for (int mt = 0; mt < 4; ++mt)
        rowA[mt] = (uint32_t)(warpM * 64 + mt * 16 + (lane & 15)) * 128;
    #pragma unroll
    for (int c = 0; c < 2; ++c)
        rowB[c] = (uint32_t)(warpN * 32 + c * 16 + (lane & 15)) * 128;

    for (int it = 0; it < NITER; ++it) {
        int buf = it & 1;
        if (it + 1 < NITER) { load_tiles(it + 1, buf ^ 1); cp_commit(); CP_WAIT1(); }
        else                { CP_WAIT0(); }
        __syncthreads();
        const uint32_t sAh = smem0 + buf * BUFB;
        const uint32_t sAl = sAh + ASZ;
        const uint32_t sBh = sAl + ASZ;
        const uint32_t sBl = sBh + BSZ;
        #pragma unroll
        for (int ks = 0; ks < 4; ++ks) {
            const uint32_t kb = ((uint32_t)(ks * 32) + kbBase) ^ aSwz;
            uint32_t ah[4][4], al[4][4];
            #pragma unroll
            for (int mt = 0; mt < 4; ++mt) {
                LDM4(ah[mt], sAh + rowA[mt] + kb);
                LDM4(al[mt], sAl + rowA[mt] + kb);
            }
            #pragma unroll
            for (int c = 0; c < 2; ++c) {
                uint32_t bh[4], bl[4];
                LDM4(bh, sBh + rowB[c] + kb);
                LDM4(bl, sBl + rowB[c] + kb);
                #pragma unroll
                for (int mt = 0; mt < 4; ++mt) {
                    MMA3(acc[mt][2 * c], acc[mt][2 * c + 1], ah[mt], al[mt], bh, bl);
                }
            }
        }
        if (it + 1 < NITER) __syncthreads();
    }

    const int tr = lane >> 2, tc = (lane & 3) * 2;
    #pragma unroll
    for (int mt = 0; mt < 4; ++mt)
        #pragma unroll
        for (int half = 0; half < 2; ++half) {
            int m = m0 + warpM * 64 + mt * 16 + tr + half * 8;
            #pragma unroll
            for (int nt = 0; nt < 4; ++nt) {
                int n = n0 + warpN * 32 + nt * 8 + tc;
                float v0 = fmaxf(acc[mt][nt][half * 2 + 0] + bias[n], 0.f);
                float v1 = fmaxf(acc[mt][nt][half * 2 + 1] + bias[n + 1], 0.f);
                *reinterpret_cast<float2*>(Of32 + (size_t)m * 1024 + n) =
                    make_float2(v0, v1);
            }
        }
}

// ---------------------------------------------------------------------------
// Weight prep + branch + fc2 (unchanged, validated)
// ---------------------------------------------------------------------------
#define PREP_SA   4096
#define PREP_C1   (128 * 192)
#define PREP_C2   (256 * 384)
#define PREP_C3   (256 * 768)
#define PREP_WPT  4096
#define PREP_WB1  4096
#define PREP_WB2  8192
#define PREP_WB3  32768
#define PREP_SMALL (PREP_SA + PREP_C1 + PREP_C2 + PREP_C3 + PREP_WPT + \
                    PREP_WB1 + PREP_WB2 + PREP_WB3)

__global__ void prep_small_kernel(
    const float* __restrict__ Wp, const float* __restrict__ W1,
    const float* __restrict__ W2, const float* __restrict__ W3,
    const float* __restrict__ Wb1, const float* __restrict__ Wb2,
    const float* __restrict__ Wb3,
    bf16* wah, bf16* wal, bf16* w1h, bf16* w1l, bf16* w2h, bf16* w2l,
    bf16* w3h, bf16* w3l,
    float* wpt, float* wb1t, float* wb2t, float* wb3t)
{
    int idx = blockIdx.x * 256 + threadIdx.x;
    if (idx >= PREP_SMALL) return;
    bf16 h, l;
    if (idx < PREP_SA) {
        int p = idx >> 6, i = idx & 63;
        split2(Wp[p * 128 + i * 2 + 1], h, l);
        wah[idx] = h; wal[idx] = l;
        return;
    }
    idx -= PREP_SA;
    if (idx < PREP_C1) {
        int o = idx / 192, rem = idx - o * 192;
        int i = rem / 3, j = rem - i * 3;
        split2(W1[idx], h, l);
        w1h[o * 192 + j * 64 + i] = h; w1l[o * 192 + j * 64 + i] = l;
        return;
    }
    idx -= PREP_C1;
    if (idx < PREP_C2) {
        int o = idx / 384, rem = idx - o * 384;
        int i = rem / 3, j = rem - i * 3;
        split2(W2[idx], h, l);
        w2h[o * 384 + j * 128 + i] = h; w2l[o * 384 + j * 128 + i] = l;
        return;
    }
    idx -= PREP_C2;
    if (idx < PREP_C3) {
        int o = idx / 768, rem = idx - o * 768;
        int i = rem / 3, j = rem - i * 3;
        split2(W3[idx], h, l);
        w3h[o * 768 + j * 256 + i] = h; w3l[o * 768 + j * 256 + i] = l;
        return;
    }
    idx -= PREP_C3;
    if (idx < PREP_WPT) { int i = idx >> 6, p = idx & 63; wpt[idx] = Wp[p * 128 + i * 2]; return; }
    idx -= PREP_WPT;
    if (idx < PREP_WB1) { int i = idx >> 6, n = idx & 63; wb1t[idx] = Wb1[n * 64 + i]; return; }
    idx -= PREP_WB1;
    if (idx < PREP_WB2) { int i = idx >> 7, n = idx & 127; wb2t[idx] = Wb2[n * 64 + i]; return; }
    idx -= PREP_WB2;
    { int i = idx >> 8, n = idx & 255; wb3t[idx] = Wb3[n * 128 + i]; }
}

__global__ void __launch_bounds__(256) prep_fc_kernel(
    const float* __restrict__ Wfc1, bf16* __restrict__ wfh,
    bf16* __restrict__ wfl)
{
    extern __shared__ float s[];
    const int n = blockIdx.x, tid = threadIdx.x;
    const float* src = Wfc1 + (size_t)n * 16640;
    for (int k = tid; k < 16384; k += 256) {
        int c = k >> 6, p = k & 63;
        s[c * 65 + p] = src[k];
    }
    __syncthreads();
    bf16* dh = wfh + (size_t)n * 16640;
    bf16* dl = wfl + (size_t)n * 16640;
    for (int k2 = tid; k2 < 16384; k2 += 256) {
        int p = k2 >> 8, c = k2 & 255;
        bf16 h, l;
        split2(s[c * 65 + p], h, l);
        dh[k2] = h; dl[k2] = l;
    }
    for (int k2 = 16384 + tid; k2 < 16640; k2 += 256) {
        bf16 h, l;
        split2(src[k2], h, l);
        dh[k2] = h; dl[k2] = l;
    }
}

#define BB 16
__global__ void __launch_bounds__(256) branch_s0_kernel(
    const float* __restrict__ x,
    const float* __restrict__ wpt,  const float* __restrict__ bp,
    const float* __restrict__ wb1t, const float* __restrict__ bb1,
    const float* __restrict__ wb2t, const float* __restrict__ bb2,
    const float* __restrict__ wb3t, const float* __restrict__ bb3,
    float* __restrict__ s0, bf16* __restrict__ zh, bf16* __restrict__ zl)
{
    __shared__ float x0s[BB][64], f1s[BB][64], f2s[BB][128];
    const int tid = threadIdx.x;
    const int b0 = blockIdx.x * BB;
    #pragma unroll
    for (int t = 0; t < 4; ++t) {
        int idx = tid + t * 256;
        int bs = idx >> 6, i = idx & 63;
        x0s[bs][i] = x[(size_t)(b0 + bs) * 16384 + i];
    }
    __syncthreads();
    #pragma unroll
    for (int t = 0; t < 4; ++t) {
        int idx = tid + t * 256;
        int bs = idx >> 6, n = idx & 63;
        float a0 = bp[n], a1 = bb1[n];
        #pragma unroll 8
        for (int i = 0; i < 64; ++i) {
            float xv = x0s[bs][i];
            a0 += wpt[i * 64 + n] * xv;
            a1 += wb1t[i * 64 + n] * xv;
        }
        s0[(size_t)(b0 + bs) * 64 + n] = a0;
        f1s[bs][n] = fmaxf(a1, 0.f);
    }
    __syncthreads();
    #pragma unroll
    for (int t = 0; t < 8; ++t) {
        int idx = tid + t * 256;
        int bs = idx >> 7, n = idx & 127;
        float a = bb2[n];
        #pragma unroll 8
        for (int i = 0; i < 64; ++i) a += wb2t[i * 128 + n] * f1s[bs][i];
        f2s[bs][n] = fmaxf(a, 0.f);
    }
    __syncthreads();
    #pragma unroll
    for (int t = 0; t < 16; ++t) {
        int idx = tid + t * 256;
        int bs = idx >> 8, n = idx & 255;
        float a = bb3[n];
        #pragma unroll 8
        for (int i = 0; i < 128; ++i) a += wb3t[i * 256 + n] * f2s[bs][i];
        float v = fmaxf(a, 0.f);
        bf16 h, l;
        split2(v, h, l);
        size_t o = (size_t)(b0 + bs) * 16640 + 16384 + n;
        zh[o] = h; zl[o] = l;
    }
}

__global__ void __launch_bounds__(128) fc2_kernel(
    const float* __restrict__ f1, const float* __restrict__ W,
    const float* __restrict__ bias, float* __restrict__ out)
{
    __shared__ float red0[4], red1[4];
    const int b = blockIdx.x, tid = threadIdx.x;
    const float* hb = f1 + (size_t)b * 1024;
    float s0 = 0.f, s1 = 0.f;
    for (int k = tid; k < 1024; k += 128) {
        float v = hb[k];
        s0 += v * W[k];
        s1 += v * W[1024 + k];
    }
    #pragma unroll
    for (int off = 16; off > 0; off >>= 1) {
        s0 += __shfl_down_sync(0xffffffffu, s0, off);
        s1 += __shfl_down_sync(0xffffffffu, s1, off);
    }
    if ((tid & 31) == 0) { red0[tid >> 5] = s0; red1[tid >> 5] = s1; }
    __syncthreads();
    if (tid == 0) {
        out[b * 2 + 0] = red0[0] + red0[1] + red0[2] + red0[3] + bias[0];
        out[b * 2 + 1] = red1[0] + red1[1] + red1[2] + red1[3] + bias[1];
    }
}

// ---------------------------------------------------------------------------
// Launch
// ---------------------------------------------------------------------------
extern "C" void kernel_launch(void* const* d_in, const int* in_sizes, int n_in,
                              void* d_out, int out_size)
{
    const float* x    = (const float*)d_in[0];
    const float* Wp   = (const float*)d_in[1];
    const float* bp   = (const float*)d_in[2];
    const float* W1   = (const float*)d_in[3];
    const float* b1   = (const float*)d_in[4];
    const float* W2   = (const float*)d_in[5];
    const float* b2   = (const float*)d_in[6];
    const float* W3   = (const float*)d_in[7];
    const float* b3   = (const float*)d_in[8];
    const float* Wb1  = (const float*)d_in[9];
    const float* bb1  = (const float*)d_in[10];
    const float* Wb2  = (const float*)d_in[11];
    const float* bb2  = (const float*)d_in[12];
    const float* Wb3  = (const float*)d_in[13];
    const float* bb3  = (const float*)d_in[14];
    const float* Wfc1 = (const float*)d_in[15];
    const float* bfc1 = (const float*)d_in[16];
    const float* Wfc2 = (const float*)d_in[17];
    const float* bfc2 = (const float*)d_in[18];
    float* out = (float*)d_out;

    static void *zh, *zl, *f1, *s0;
    static void *wah, *wal, *w1h, *w1l, *w2h, *w2l, *w3h, *w3l, *wfh, *wfl;
    static void *wpt, *wb1t, *wb2t, *wb3t;
    static bool init = false;
    if (!init) {
        cudaGetSymbolAddress(&zh,  g_zh);  cudaGetSymbolAddress(&zl,  g_zl);
        cudaGetSymbolAddress(&f1,  g_f1);  cudaGetSymbolAddress(&s0,  g_s0);
        cudaGetSymbolAddress(&wah, g_wah); cudaGetSymbolAddress(&wal, g_wal);
        cudaGetSymbolAddress(&w1h, g_w1h); cudaGetSymbolAddress(&w1l, g_w1l);
        cudaGetSymbolAddress(&w2h, g_w2h); cudaGetSymbolAddress(&w2l, g_w2l);
        cudaGetSymbolAddress(&w3h, g_w3h); cudaGetSymbolAddress(&w3l, g_w3l);
        cudaGetSymbolAddress(&wfh, g_wfh); cudaGetSymbolAddress(&wfl, g_wfl);
        cudaGetSymbolAddress(&wpt, g_wpt); cudaGetSymbolAddress(&wb1t, g_wb1t);
        cudaGetSymbolAddress(&wb2t, g_wb2t); cudaGetSymbolAddress(&wb3t, g_wb3t);
        cudaFuncSetAttribute(fused_conv_kernel,
                             cudaFuncAttributeMaxDynamicSharedMemorySize, FUSED_SMEM);
        cudaFuncSetAttribute(fc1_kernel,
                             cudaFuncAttributeMaxDynamicSharedMemorySize, 131072);
        cudaFuncSetAttribute(prep_fc_kernel,
                             cudaFuncAttributeMaxDynamicSharedMemorySize, 256 * 65 * 4);
        init = true;
    }

    prep_small_kernel<<<(PREP_SMALL + 255) / 256, 256>>>(
        Wp, W1, W2, W3, Wb1, Wb2, Wb3,
        (bf16*)wah, (bf16*)wal, (bf16*)w1h, (bf16*)w1l, (bf16*)w2h, (bf16*)w2l,
        (bf16*)w3h, (bf16*)w3l,
        (float*)wpt, (float*)wb1t, (float*)wb2t, (float*)wb3t);
    prep_fc_kernel<<<1024, 256, 256 * 65 * 4>>>(Wfc1, (bf16*)wfh, (bf16*)wfl);

    branch_s0_kernel<<<2048 / BB, 256>>>(
        x, (const float*)wpt, bp, (const float*)wb1t, bb1,
        (const float*)wb2t, bb2, (const float*)wb3t, bb3,
        (float*)s0, (bf16*)zh, (bf16*)zl);

    fused_conv_kernel<<<2048, 512, FUSED_SMEM>>>(
        x, (const float*)s0,
        (const bf16*)wah, (const bf16*)wal, (const bf16*)w1h, (const bf16*)w1l,
        (const bf16*)w2h, (const bf16*)w2l, (const bf16*)w3h, (const bf16*)w3l,
        b1, b2, b3, (bf16*)zh, (bf16*)zl);

    fc1_kernel<<<dim3(8, 16), 256, 131072>>>(
        (const bf16*)zh, (const bf16*)zl, (const bf16*)wfh, (const bf16*)wfl,
        bfc1, (float*)f1);

    fc2_kernel<<<2048, 128>>>((const float*)f1, Wfc2, bfc2, out);
}

// round 12
// speedup vs baseline: 1.0168x; 1.0049x over previous
#include <cuda_runtime.h>
#include <cuda_bf16.h>
#include <cstdint>

typedef __nv_bfloat16 bf16;

// ---------------------------------------------------------------------------
__device__ __align__(1024) bf16 g_h0h[(size_t)2048 * 255 * 64];
__device__ __align__(1024) bf16 g_h0l[(size_t)2048 * 255 * 64];
__device__ __align__(1024) bf16 g_h1h[(size_t)2048 * 255 * 128];
__device__ __align__(1024) bf16 g_h1l[(size_t)2048 * 255 * 128];
__device__ __align__(1024) bf16 g_h2h[(size_t)2048 * 128 * 256];
__device__ __align__(1024) bf16 g_h2l[(size_t)2048 * 128 * 256];
__device__ __align__(1024) bf16 g_zh [(size_t)2048 * 16640];
__device__ __align__(1024) bf16 g_zl [(size_t)2048 * 16640];
__device__ __align__(1024) float g_f1p[(size_t)2 * 2048 * 1024];
__device__ __align__(1024) float g_s0[2048 * 64];
__device__ __align__(1024) bf16 g_wah[64 * 64],   g_wal[64 * 64];
__device__ __align__(1024) bf16 g_w1h[128 * 192], g_w1l[128 * 192];
__device__ __align__(1024) bf16 g_w2h[256 * 384], g_w2l[256 * 384];
__device__ __align__(1024) bf16 g_w3h[256 * 768], g_w3l[256 * 768];
__device__ __align__(1024) bf16 g_wfh[(size_t)1024 * 16640];
__device__ __align__(1024) bf16 g_wfl[(size_t)1024 * 16640];
__device__ __align__(1024) float g_wpt [64 * 64];
__device__ __align__(1024) float g_wb1t[64 * 64];
__device__ __align__(1024) float g_wb2t[64 * 128];
__device__ __align__(1024) float g_wb3t[128 * 256];

// ---------------------------------------------------------------------------
__device__ __forceinline__ uint32_t cvta_smem(const void* p) {
    return (uint32_t)__cvta_generic_to_shared(p);
}
__device__ __forceinline__ void cpa16(uint32_t dst, const void* src, int sz) {
    asm volatile("cp.async.cg.shared.global [%0], [%1], 16, %2;"
                 :: "r"(dst), "l"(src), "r"(sz) : "memory");
}
__device__ __forceinline__ void cp_commit() {
    asm volatile("cp.async.commit_group;" ::: "memory");
}
#define CP_WAIT1() asm volatile("cp.async.wait_group 1;" ::: "memory")
#define CP_WAIT0() asm volatile("cp.async.wait_group 0;" ::: "memory")
#define LDM4(r, addr)                                                         \
    asm volatile("ldmatrix.sync.aligned.m8n8.x4.shared.b16 "                  \
                 "{%0,%1,%2,%3}, [%4];"                                       \
                 : "=r"((r)[0]), "=r"((r)[1]), "=r"((r)[2]), "=r"((r)[3])     \
                 : "r"(addr))

__device__ __forceinline__ void mma16816(float* d, const uint32_t* a,
                                         uint32_t b0, uint32_t b1) {
    asm volatile(
        "mma.sync.aligned.m16n8k16.row.col.f32.bf16.bf16.f32 "
        "{%0,%1,%2,%3}, {%4,%5,%6,%7}, {%8,%9}, {%0,%1,%2,%3};"
        : "+f"(d[0]), "+f"(d[1]), "+f"(d[2]), "+f"(d[3])
        : "r"(a[0]), "r"(a[1]), "r"(a[2]), "r"(a[3]), "r"(b0), "r"(b1));
}
__device__ __forceinline__ void split2(float v, bf16& h, bf16& l) {
    h = __float2bfloat16(v);
    l = __float2bfloat16(v - __bfloat162float(h));
}
__device__ __forceinline__ uint32_t pack2(bf16 a, bf16 b) {
    return (uint32_t)__bfloat16_as_ushort(a) |
           ((uint32_t)__bfloat16_as_ushort(b) << 16);
}
#define MMA3(acc0, acc1, AH, AL, BH, BL)                                      \
    mma16816(acc0, AH, BH[0], BH[2]); mma16816(acc1, AH, BH[1], BH[3]);       \
    mma16816(acc0, AH, BL[0], BL[2]); mma16816(acc1, AH, BL[1], BL[3]);       \
    mma16816(acc0, AL, BH[0], BH[2]); mma16816(acc1, AL, BH[1], BH[3]);

// ---------------------------------------------------------------------------
// R8 conv/stage-A GEMM template (proven): 256 thr, CTA 128 x NT, BK=64,
// warps 2M x 4N (warp 64 x NT/4). OUTMODE: 0 = out[m*NS+n]; 2 = z layout.
// ---------------------------------------------------------------------------
template<int KTOT, int NT, int CIN, int LIN, int LOUT, int STRIDE, int ROFF,
         int OUTMODE, int NS, bool ROWBIAS, bool AF32, bool OUTF32>
__global__ void __launch_bounds__(256, 1)
gemm_kernel(const float* __restrict__ Af32,
            const bf16* __restrict__ Ahi, const bf16* __restrict__ Alo,
            const bf16* __restrict__ Whi, const bf16* __restrict__ Wlo,
            const float* __restrict__ bias,
            float* __restrict__ Of32, bf16* __restrict__ Ohi,
            bf16* __restrict__ Olo)
{
    constexpr int BK = 64;
    constexpr int NITER = KTOT / BK;
    constexpr int ASZ = 128 * 128;
    constexpr int BSZ = NT * 128;
    constexpr int BUFB = 2 * ASZ + 2 * BSZ;
    constexpr int NH = NT / 4;
    constexpr int NI = NH / 8;
    constexpr int NL = NH / 16;
    constexpr int BREP = NT / 32;

    extern __shared__ __align__(1024) char smem_c[];
    const uint32_t smem0 = cvta_smem(smem_c);
    const int tid = threadIdx.x;
    const int lane = tid & 31;
    const int wid = tid >> 5;
    const int warpM = wid >> 2, warpN = wid & 3;
    const int n0 = blockIdx.x * NT, m0 = blockIdx.y * 128;

    float acc[4][NI][4];
    #pragma unroll
    for (int mt = 0; mt < 4; ++mt)
        #pragma unroll
        for (int nt = 0; nt < NI; ++nt)
            #pragma unroll
            for (int e = 0; e < 4; ++e) acc[mt][nt][e] = 0.f;

    auto load_tiles = [&](int it, int buf) {
        const int k0 = it * BK;
        const uint32_t sb = smem0 + buf * BUFB;
        #pragma unroll
        for (int rep = 0; rep < 4; ++rep) {
            int v = tid + rep * 256;
            int row = v >> 3, q = v & 7;
            int m = m0 + row;
            int b = m / LOUT, p = m - b * LOUT;
            int k = k0 + q * 8;
            int j = k / CIN, i = k - j * CIN;
            int r = STRIDE * p + j + ROFF;
            bool ok = (r >= 0) && (r < LIN);
            size_t off = (size_t)b * ((size_t)LIN * CIN) + (size_t)r * CIN + i;
            uint32_t so = row * 128 + ((q * 16) ^ ((row & 7) << 4));
            int sz = ok ? 16 : 0;
            cpa16(sb + so, Ahi + off, sz);
            cpa16(sb + ASZ + so, Alo + off, sz);
        }
        #pragma unroll
        for (int rep = 0; rep < BREP; ++rep) {
            int v = tid + rep * 256;
            int n = v >> 3, q = v & 7;
            size_t off = (size_t)(n0 + n) * KTOT + k0 + q * 8;
            uint32_t so = n * 128 + ((q * 16) ^ ((n & 7) << 4));
            cpa16(sb + 2 * ASZ + so, Whi + off, 16);
            cpa16(sb + 2 * ASZ + BSZ + so, Wlo + off, 16);
        }
    };

    if constexpr (AF32) {
        #pragma unroll
        for (int rep = 0; rep < 8; ++rep) {
            int v = tid + rep * 256;
            int row = v >> 4, q = v & 15;
            int m = m0 + row;
            int b = m / LOUT, p = m - b * LOUT;
            int i = q * 4;
            int r = p + ROFF;
            bool ok = (r >= 0) && (r < LIN);
            float4 val = ok ? *reinterpret_cast<const float4*>(
                                  Af32 + (size_t)b * ((size_t)LIN * CIN) +
                                  (size_t)r * CIN + i)
                            : make_float4(0.f, 0.f, 0.f, 0.f);
            bf16 h0, h1, h2, h3, l0, l1, l2, l3;
            split2(val.x, h0, l0); split2(val.y, h1, l1);
            split2(val.z, h2, l2); split2(val.w, h3, l3);
            uint32_t so = row * 128 + ((q * 8) ^ ((row & 7) << 4));
            *reinterpret_cast<uint2*>(smem_c + so) =
                make_uint2(pack2(h0, h1), pack2(h2, h3));
            *reinterpret_cast<uint2*>(smem_c + ASZ + so) =
                make_uint2(pack2(l0, l1), pack2(l2, l3));
        }
        #pragma unroll
        for (int rep = 0; rep < BREP; ++rep) {
            int v = tid + rep * 256;
            int n = v >> 3, q = v & 7;
            size_t off = (size_t)(n0 + n) * KTOT + q * 8;
            uint32_t so = n * 128 + ((q * 16) ^ ((n & 7) << 4));
            *reinterpret_cast<uint4*>(smem_c + 2 * ASZ + so) =
                *reinterpret_cast<const uint4*>(Whi + off);
            *reinterpret_cast<uint4*>(smem_c + 2 * ASZ + BSZ + so) =
                *reinterpret_cast<const uint4*>(Wlo + off);
        }
        __syncthreads();
    } else {
        load_tiles(0, 0);
        cp_commit();
    }

    const uint32_t aSwz = (uint32_t)(lane & 7) << 4;
    const uint32_t kbBase = (uint32_t)(lane >> 4) << 4;
    uint32_t rowA[4], rowB[NL];
    #pragma unroll
    for (int mt = 0; mt < 4; ++mt)
        rowA[mt] = (uint32_t)(warpM * 64 + mt * 16 + (lane & 15)) * 128;
    #pragma unroll
    for (int c = 0; c < NL; ++c)
        rowB[c] = (uint32_t)(warpN * NH + c * 16 + (lane & 15)) * 128;

    for (int it = 0; it < NITER; ++it) {
        int buf = it & 1;
        if constexpr (!AF32) {
            if (it + 1 < NITER) {
                load_tiles(it + 1, buf ^ 1);
                cp_commit();
                CP_WAIT1();
            } else {
                CP_WAIT0();
            }
            __syncthreads();
        } else buf = 0;

        const uint32_t sAh = smem0 + buf * BUFB;
        const uint32_t sAl = sAh + ASZ;
        const uint32_t sBh = sAl + ASZ;
        const uint32_t sBl = sBh + BSZ;

        #pragma unroll
        for (int ks = 0; ks < 4; ++ks) {
            const uint32_t kb = ((uint32_t)(ks * 32) + kbBase) ^ aSwz;
            uint32_t ah[4][4], al[4][4];
            #pragma unroll
            for (int mt = 0; mt < 4; ++mt) {
                LDM4(ah[mt], sAh + rowA[mt] + kb);
                LDM4(al[mt], sAl + rowA[mt] + kb);
            }
            #pragma unroll
            for (int c = 0; c < NL; ++c) {
                uint32_t bh[4], bl[4];
                LDM4(bh, sBh + rowB[c] + kb);
                LDM4(bl, sBl + rowB[c] + kb);
                #pragma unroll
                for (int mt = 0; mt < 4; ++mt) {
                    MMA3(acc[mt][2 * c], acc[mt][2 * c + 1], ah[mt], al[mt], bh, bl);
                }
            }
        }
        if constexpr (!AF32) {
            if (it + 1 < NITER) __syncthreads();
        }
    }

    const int tr = lane >> 2, tc = (lane & 3) * 2;
    #pragma unroll
    for (int mt = 0; mt < 4; ++mt)
        #pragma unroll
        for (int half = 0; half < 2; ++half) {
            const int m = m0 + warpM * 64 + mt * 16 + tr + half * 8;
            const int bb = m / LOUT;
            const int pp = m - bb * LOUT;
            #pragma unroll
            for (int nt = 0; nt < NI; ++nt) {
                const int n = n0 + warpN * NH + nt * 8 + tc;
                float b0, b1;
                if constexpr (ROWBIAS) {
                    b0 = bias[(size_t)bb * 64 + n];
                    b1 = bias[(size_t)bb * 64 + n + 1];
                } else {
                    b0 = bias[n]; b1 = bias[n + 1];
                }
                const float v0 = fmaxf(acc[mt][nt][half * 2 + 0] + b0, 0.f);
                const float v1 = fmaxf(acc[mt][nt][half * 2 + 1] + b1, 0.f);
                size_t o;
                if constexpr (OUTMODE == 0) o = (size_t)m * NS + n;
                else o = (size_t)bb * 16640 + (size_t)pp * 256 + n;
                if constexpr (OUTF32) {
                    *reinterpret_cast<float2*>(Of32 + o) = make_float2(v0, v1);
                } else {
                    bf16 h0, h1, l0, l1;
                    split2(v0, h0, l0); split2(v1, h1, l1);
                    *reinterpret_cast<uint32_t*>(Ohi + o) = pack2(h0, h1);
                    *reinterpret_cast<uint32_t*>(Olo + o) = pack2(l0, l1);
                }
            }
        }
}

// ---------------------------------------------------------------------------
// fc1 k-split: 128 thr, CTA 128x128, warps 2M x 2N (warp 64x64, 85B/MMA),
// BK=32, 80B padded rows (conflict-free ldmatrix), partials -> g_f1p[kb].
// grid (8 n, 16 m, 2 k). 80KB smem -> 2 CTAs/SM.
// ---------------------------------------------------------------------------
#define FCROW 80u
#define FCPL  10240u            // 128 rows * 80B
#define FCBUF 40960u            // Ah,Al,Bh,Bl planes
__global__ void __launch_bounds__(128, 2)
fc1_kernel(const bf16* __restrict__ Ahi, const bf16* __restrict__ Alo,
           const bf16* __restrict__ Whi, const bf16* __restrict__ Wlo,
           float* __restrict__ f1p)
{
    constexpr int KTOT = 16640, KHALF = 8320, NITER = KHALF / 32;
    extern __shared__ __align__(1024) char smem_c[];
    const uint32_t smem0 = cvta_smem(smem_c);
    const int tid = threadIdx.x;
    const int lane = tid & 31;
    const int wid = tid >> 5;
    const int warpM = wid >> 1, warpN = wid & 1;
    const int n0 = blockIdx.x * 128, m0 = blockIdx.y * 128;
    const int kbase = blockIdx.z * KHALF;

    float acc[4][8][4] = {};

    auto load_tiles = [&](int it, int buf) {
        const int k0 = kbase + it * 32;
        const uint32_t sb = smem0 + buf * FCBUF;
        #pragma unroll
        for (int rep = 0; rep < 8; ++rep) {        // A: 128row x 4q x 2pl
            int idx = tid + rep * 128;
            int plane = idx >> 9, v = idx & 511;
            int row = v >> 2, q = v & 3;
            size_t off = (size_t)(m0 + row) * KTOT + k0 + q * 8;
            uint32_t dst = sb + plane * FCPL + (uint32_t)row * FCROW + q * 16;
            cpa16(dst, (plane ? Alo : Ahi) + off, 16);
        }
        #pragma unroll
        for (int rep = 0; rep < 8; ++rep) {        // B
            int idx = tid + rep * 128;
            int plane = idx >> 9, v = idx & 511;
            int row = v >> 2, q = v & 3;
            size_t off = (size_t)(n0 + row) * KTOT + k0 + q * 8;
            uint32_t dst = sb + 2 * FCPL + plane * FCPL +
                           (uint32_t)row * FCROW + q * 16;
            cpa16(dst, (plane ? Wlo : Whi) + off, 16);
        }
    };
    load_tiles(0, 0); cp_commit();

    const uint32_t laneK = (uint32_t)(lane >> 4) << 4;
    const int laneM = lane & 15;
    uint32_t rowA[4], rowB[4];
    #pragma unroll
    for (int mt = 0; mt < 4; ++mt)
        rowA[mt] = (uint32_t)(warpM * 64 + mt * 16 + laneM) * FCROW;
    #pragma unroll
    for (int c = 0; c < 4; ++c)
        rowB[c] = (uint32_t)(warpN * 64 + c * 16 + laneM) * FCROW;

    for (int it = 0; it < NITER; ++it) {
        int buf = it & 1;
        if (it + 1 < NITER) { load_tiles(it + 1, buf ^ 1); cp_commit(); CP_WAIT1(); }
        else                { CP_WAIT0(); }
        __syncthreads();
        const uint32_t sAh = smem0 + buf * FCBUF;
        const uint32_t sAl = sAh + FCPL;
        const uint32_t sBh = sAl + FCPL;
        const uint32_t sBl = sBh + FCPL;
        #pragma unroll
        for (int ks = 0; ks < 2; ++ks) {
            const uint32_t kc = (uint32_t)(ks * 32) + laneK;
            uint32_t ah[4][4], al[4][4];
            #pragma unroll
            for (int mt = 0; mt < 4; ++mt) {
                LDM4(ah[mt], sAh + rowA[mt] + kc);
                LDM4(al[mt], sAl + rowA[mt] + kc);
            }
            #pragma unroll
            for (int c = 0; c < 4; ++c) {
                uint32_t bh[4], bl[4];
                LDM4(bh, sBh + rowB[c] + kc);
                LDM4(bl, sBl + rowB[c] + kc);
                #pragma unroll
                for (int mt = 0; mt < 4; ++mt) {
                    MMA3(acc[mt][2 * c], acc[mt][2 * c + 1], ah[mt], al[mt], bh, bl);
                }
            }
        }
        if (it + 1 < NITER) __syncthreads();
    }

    float* dst = f1p + (size_t)blockIdx.z * 2048 * 1024;
    const int tr = lane >> 2, tc = (lane & 3) * 2;
    #pragma unroll
    for (int mt = 0; mt < 4; ++mt)
        #pragma unroll
        for (int half = 0; half < 2; ++half) {
            int m = m0 + warpM * 64 + mt * 16 + tr + half * 8;
            #pragma unroll
            for (int nt = 0; nt < 8; ++nt) {
                int n = n0 + warpN * 64 + nt * 8 + tc;
                *reinterpret_cast<float2*>(dst + (size_t)m * 1024 + n) =
                    make_float2(acc[mt][nt][half * 2 + 0],
                                acc[mt][nt][half * 2 + 1]);
            }
        }
}

// ---------------------------------------------------------------------------
#define PREP_SA   4096
#define PREP_C1   (128 * 192)
#define PREP_C2   (256 * 384)
#define PREP_C3   (256 * 768)
#define PREP_WPT  4096
#define PREP_WB1  4096
#define PREP_WB2  8192
#define PREP_WB3  32768
#define PREP_SMALL (PREP_SA + PREP_C1 + PREP_C2 + PREP_C3 + PREP_WPT + \
                    PREP_WB1 + PREP_WB2 + PREP_WB3)

__global__ void prep_small_kernel(
    const float* __restrict__ Wp, const float* __restrict__ W1,
    const float* __restrict__ W2, const float* __restrict__ W3,
    const float* __restrict__ Wb1, const float* __restrict__ Wb2,
    const float* __restrict__ Wb3,
    bf16* wah, bf16* wal, bf16* w1h, bf16* w1l, bf16* w2h, bf16* w2l,
    bf16* w3h, bf16* w3l,
    float* wpt, float* wb1t, float* wb2t, float* wb3t)
{
    int idx = blockIdx.x * 256 + threadIdx.x;
    if (idx >= PREP_SMALL) return;
    bf16 h, l;
    if (idx < PREP_SA) {
        int p = idx >> 6, i = idx & 63;
        split2(Wp[p * 128 + i * 2 + 1], h, l);
        wah[idx] = h; wal[idx] = l; return;
    }
    idx -= PREP_SA;
    if (idx < PREP_C1) {
        int o = idx / 192, rem = idx - o * 192;
        int i = rem / 3, j = rem - i * 3;
        split2(W1[idx], h, l);
        w1h[o * 192 + j * 64 + i] = h; w1l[o * 192 + j * 64 + i] = l; return;
    }
    idx -= PREP_C1;
    if (idx < PREP_C2) {
        int o = idx / 384, rem = idx - o * 384;
        int i = rem / 3, j = rem - i * 3;
        split2(W2[idx], h, l);
        w2h[o * 384 + j * 128 + i] = h; w2l[o * 384 + j * 128 + i] = l; return;
    }
    idx -= PREP_C2;
    if (idx < PREP_C3) {
        int o = idx / 768, rem = idx - o * 768;
        int i = rem / 3, j = rem - i * 3;
        split2(W3[idx], h, l);
        w3h[o * 768 + j * 256 + i] = h; w3l[o * 768 + j * 256 + i] = l; return;
    }
    idx -= PREP_C3;
    if (idx < PREP_WPT) { int i = idx >> 6, p = idx & 63; wpt[idx] = Wp[p * 128 + i * 2]; return; }
    idx -= PREP_WPT;
    if (idx < PREP_WB1) { int i = idx >> 6, n = idx & 63; wb1t[idx] = Wb1[n * 64 + i]; return; }
    idx -= PREP_WB1;
    if (idx < PREP_WB2) { int i = idx >> 7, n = idx & 127; wb2t[idx] = Wb2[n * 64 + i]; return; }
    idx -= PREP_WB2;
    { int i = idx >> 8, n = idx & 255; wb3t[idx] = Wb3[n * 128 + i]; }
}

__global__ void __launch_bounds__(256) prep_fc_kernel(
    const float* __restrict__ Wfc1, bf16* __restrict__ wfh,
    bf16* __restrict__ wfl)
{
    extern __shared__ float s[];
    const int n = blockIdx.x, tid = threadIdx.x;
    const float* src = Wfc1 + (size_t)n * 16640;
    for (int k = tid; k < 16384; k += 256) {
        int c = k >> 6, p = k & 63;
        s[c * 65 + p] = src[k];
    }
    __syncthreads();
    bf16* dh = wfh + (size_t)n * 16640;
    bf16* dl = wfl + (size_t)n * 16640;
    for (int k2 = tid; k2 < 16384; k2 += 256) {
        int p = k2 >> 8, c = k2 & 255;
        bf16 h, l;
        split2(s[c * 65 + p], h, l);
        dh[k2] = h; dl[k2] = l;
    }
    for (int k2 = 16384 + tid; k2 < 16640; k2 += 256) {
        bf16 h, l;
        split2(src[k2], h, l);
        dh[k2] = h; dl[k2] = l;
    }
}

#define BB 16
__global__ void __launch_bounds__(256) branch_s0_kernel(
    const float* __restrict__ x,
    const float* __restrict__ wpt,  const float* __restrict__ bp,
    const float* __restrict__ wb1t, const float* __restrict__ bb1,
    const float* __restrict__ wb2t, const float* __restrict__ bb2,
    const float* __restrict__ wb3t, const float* __restrict__ bb3,
    float* __restrict__ s0, bf16* __restrict__ zh, bf16* __restrict__ zl)
{
    __shared__ float x0s[BB][64], f1s[BB][64], f2s[BB][128];
    const int tid = threadIdx.x;
    const int b0 = blockIdx.x * BB;
    #pragma unroll
    for (int t = 0; t < 4; ++t) {
        int idx = tid + t * 256;
        int bs = idx >> 6, i = idx & 63;
        x0s[bs][i] = x[(size_t)(b0 + bs) * 16384 + i];
    }
    __syncthreads();
    #pragma unroll
    for (int t = 0; t < 4; ++t) {
        int idx = tid + t * 256;
        int bs = idx >> 6, n = idx & 63;
        float a0 = bp[n], a1 = bb1[n];
        #pragma unroll 8
        for (int i = 0; i < 64; ++i) {
            float xv = x0s[bs][i];
            a0 += wpt[i * 64 + n] * xv;
            a1 += wb1t[i * 64 + n] * xv;
        }
        s0[(size_t)(b0 + bs) * 64 + n] = a0;
        f1s[bs][n] = fmaxf(a1, 0.f);
    }
    __syncthreads();
    #pragma unroll
    for (int t = 0; t < 8; ++t) {
        int idx = tid + t * 256;
        int bs = idx >> 7, n = idx & 127;
        float a = bb2[n];
        #pragma unroll 8
        for (int i = 0; i < 64; ++i) a += wb2t[i * 128 + n] * f1s[bs][i];
        f2s[bs][n] = fmaxf(a, 0.f);
    }
    __syncthreads();
    #pragma unroll
    for (int t = 0; t < 16; ++t) {
        int idx = tid + t * 256;
        int bs = idx >> 8, n = idx & 255;
        float a = bb3[n];
        #pragma unroll 8
        for (int i = 0; i < 128; ++i) a += wb3t[i * 256 + n] * f2s[bs][i];
        float v = fmaxf(a, 0.f);
        bf16 h, l;
        split2(v, h, l);
        size_t o = (size_t)(b0 + bs) * 16640 + 16384 + n;
        zh[o] = h; zl[o] = l;
    }
}

// fc2 reads both fc1 partials; applies bias+relu here.
__global__ void __launch_bounds__(128) fc2_kernel(
    const float* __restrict__ f1p, const float* __restrict__ bfc1,
    const float* __restrict__ W, const float* __restrict__ bias,
    float* __restrict__ out)
{
    __shared__ float red0[4], red1[4];
    const int b = blockIdx.x, tid = threadIdx.x;
    const float* p0 = f1p + (size_t)b * 1024;
    const float* p1 = f1p + (size_t)2048 * 1024 + (size_t)b * 1024;
    float s0 = 0.f, s1 = 0.f;
    for (int k = tid; k < 1024; k += 128) {
        float v = fmaxf(p0[k] + p1[k] + bfc1[k], 0.f);
        s0 += v * W[k];
        s1 += v * W[1024 + k];
    }
    #pragma unroll
    for (int off = 16; off > 0; off >>= 1) {
        s0 += __shfl_down_sync(0xffffffffu, s0, off);
        s1 += __shfl_down_sync(0xffffffffu, s1, off);
    }
    if ((tid & 31) == 0) { red0[tid >> 5] = s0; red1[tid >> 5] = s1; }
    __syncthreads();
    if (tid == 0) {
        out[b * 2 + 0] = red0[0] + red0[1] + red0[2] + red0[3] + bias[0];
        out[b * 2 + 1] = red1[0] + red1[1] + red1[2] + red1[3] + bias[1];
    }
}

// ---------------------------------------------------------------------------
extern "C" void kernel_launch(void* const* d_in, const int* in_sizes, int n_in,
                              void* d_out, int out_size)
{
    const float* x    = (const float*)d_in[0];
    const float* Wp   = (const float*)d_in[1];
    const float* bp   = (const float*)d_in[2];
    const float* W1   = (const float*)d_in[3];
    const float* b1   = (const float*)d_in[4];
    const float* W2   = (const float*)d_in[5];
    const float* b2   = (const float*)d_in[6];
    const float* W3   = (const float*)d_in[7];
    const float* b3   = (const float*)d_in[8];
    const float* Wb1  = (const float*)d_in[9];
    const float* bb1  = (const float*)d_in[10];
    const float* Wb2  = (const float*)d_in[11];
    const float* bb2  = (const float*)d_in[12];
    const float* Wb3  = (const float*)d_in[13];
    const float* bb3  = (const float*)d_in[14];
    const float* Wfc1 = (const float*)d_in[15];
    const float* bfc1 = (const float*)d_in[16];
    const float* Wfc2 = (const float*)d_in[17];
    const float* bfc2 = (const float*)d_in[18];
    float* out = (float*)d_out;

    static void *h0h, *h0l, *h1h, *h1l, *h2h, *h2l, *zh, *zl, *f1p, *s0;
    static void *wah, *wal, *w1h, *w1l, *w2h, *w2l, *w3h, *w3l, *wfh, *wfl;
    static void *wpt, *wb1t, *wb2t, *wb3t;
    static bool init = false;
    if (!init) {
        cudaGetSymbolAddress(&h0h, g_h0h); cudaGetSymbolAddress(&h0l, g_h0l);
        cudaGetSymbolAddress(&h1h, g_h1h); cudaGetSymbolAddress(&h1l, g_h1l);
        cudaGetSymbolAddress(&h2h, g_h2h); cudaGetSymbolAddress(&h2l, g_h2l);
        cudaGetSymbolAddress(&zh,  g_zh);  cudaGetSymbolAddress(&zl,  g_zl);
        cudaGetSymbolAddress(&f1p, g_f1p); cudaGetSymbolAddress(&s0,  g_s0);
        cudaGetSymbolAddress(&wah, g_wah); cudaGetSymbolAddress(&wal, g_wal);
        cudaGetSymbolAddress(&w1h, g_w1h); cudaGetSymbolAddress(&w1l, g_w1l);
        cudaGetSymbolAddress(&w2h, g_w2h); cudaGetSymbolAddress(&w2l, g_w2l);
        cudaGetSymbolAddress(&w3h, g_w3h); cudaGetSymbolAddress(&w3l, g_w3l);
        cudaGetSymbolAddress(&wfh, g_wfh); cudaGetSymbolAddress(&wfl, g_wfl);
        cudaGetSymbolAddress(&wpt, g_wpt); cudaGetSymbolAddress(&wb1t, g_wb1t);
        cudaGetSymbolAddress(&wb2t, g_wb2t); cudaGetSymbolAddress(&wb3t, g_wb3t);
        auto setsm = [](const void* f, int bytes) {
            cudaFuncSetAttribute(f, cudaFuncAttributeMaxDynamicSharedMemorySize, bytes);
        };
        setsm((const void*)gemm_kernel<64, 64, 64, 256, 255, 1, 1, 0, 64, true, true, false>, 49152);
        setsm((const void*)gemm_kernel<192, 128, 64, 255, 255, 1, -1, 0, 128, false, false, false>, 131072);
        setsm((const void*)gemm_kernel<384, 256, 128, 255, 128, 2, -1, 0, 256, false, false, false>, 196608);
        setsm((const void*)gemm_kernel<768, 256, 256, 128, 64, 2, -1, 2, 0, false, false, false>, 196608);
        setsm((const void*)fc1_kernel, 2 * FCBUF);
        setsm((const void*)prep_fc_kernel, 256 * 65 * 4);
        init = true;
    }

    prep_small_kernel<<<(PREP_SMALL + 255) / 256, 256>>>(
        Wp, W1, W2, W3, Wb1, Wb2, Wb3,
        (bf16*)wah, (bf16*)wal, (bf16*)w1h, (bf16*)w1l, (bf16*)w2h, (bf16*)w2l,
        (bf16*)w3h, (bf16*)w3l,
        (float*)wpt, (float*)wb1t, (float*)wb2t, (float*)wb3t);
    prep_fc_kernel<<<1024, 256, 256 * 65 * 4>>>(Wfc1, (bf16*)wfh, (bf16*)wfl);

    branch_s0_kernel<<<2048 / BB, 256>>>(
        x, (const float*)wpt, bp, (const float*)wb1t, bb1,
        (const float*)wb2t, bb2, (const float*)wb3t, bb3,
        (float*)s0, (bf16*)zh, (bf16*)zl);

    gemm_kernel<64, 64, 64, 256, 255, 1, 1, 0, 64, true, true, false>
        <<<dim3(1, 4080), 256, 49152>>>(
            x, nullptr, nullptr, (const bf16*)wah, (const bf16*)wal,
            (const float*)s0, nullptr, (bf16*)h0h, (bf16*)h0l);

    gemm_kernel<192, 128, 64, 255, 255, 1, -1, 0, 128, false, false, false>
        <<<dim3(1, 4080), 256, 131072>>>(
            nullptr, (const bf16*)h0h, (const bf16*)h0l,
            (const bf16*)w1h, (const bf16*)w1l, b1,
            nullptr, (bf16*)h1h, (bf16*)h1l);

    gemm_kernel<384, 256, 128, 255, 128, 2, -1, 0, 256, false, false, false>
        <<<dim3(1, 2048), 256, 196608>>>(
            nullptr, (const bf16*)h1h, (const bf16*)h1l,
            (const bf16*)w2h, (const bf16*)w2l, b2,
            nullptr, (bf16*)h2h, (bf16*)h2l);

    gemm_kernel<768, 256, 256, 128, 64, 2, -1, 2, 0, false, false, false>
        <<<dim3(1, 1024), 256, 196608>>>(
            nullptr, (const bf16*)h2h, (const bf16*)h2l,
            (const bf16*)w3h, (const bf16*)w3l, b3,
            nullptr, (bf16*)zh, (bf16*)zl);

    fc1_kernel<<<dim3(8, 16, 2), 128, 2 * FCBUF>>>(
        (const bf16*)zh, (const bf16*)zl, (const bf16*)wfh, (const bf16*)wfl,
        (float*)f1p);

    fc2_kernel<<<2048, 128>>>((const float*)f1p, bfc1, Wfc2, bfc2, out);
}

// round 13
// speedup vs baseline: 1.0756x; 1.0578x over previous
#include <cuda_runtime.h>
#include <cuda_bf16.h>
#include <cstdint>

typedef __nv_bfloat16 bf16;

// ---------------------------------------------------------------------------
__device__ __align__(1024) bf16 g_h0h[(size_t)2048 * 255 * 64];
__device__ __align__(1024) bf16 g_h0l[(size_t)2048 * 255 * 64];
__device__ __align__(1024) bf16 g_h1h[(size_t)2048 * 255 * 128];
__device__ __align__(1024) bf16 g_h1l[(size_t)2048 * 255 * 128];
__device__ __align__(1024) bf16 g_h2h[(size_t)2048 * 128 * 256];
__device__ __align__(1024) bf16 g_h2l[(size_t)2048 * 128 * 256];
__device__ __align__(1024) bf16 g_zh [(size_t)2048 * 16640];
__device__ __align__(1024) bf16 g_zl [(size_t)2048 * 16640];
__device__ __align__(1024) float g_f1[(size_t)2048 * 1024];
__device__ __align__(1024) float g_s0[2048 * 64];
__device__ __align__(1024) bf16 g_wah[64 * 64],   g_wal[64 * 64];
__device__ __align__(1024) bf16 g_w1h[128 * 192], g_w1l[128 * 192];
__device__ __align__(1024) bf16 g_w2h[256 * 384], g_w2l[256 * 384];
__device__ __align__(1024) bf16 g_w3h[256 * 768], g_w3l[256 * 768];
__device__ __align__(1024) bf16 g_wfh[(size_t)1024 * 16640];
__device__ __align__(1024) bf16 g_wfl[(size_t)1024 * 16640];
__device__ __align__(1024) float g_wpt [64 * 64];
__device__ __align__(1024) float g_wb1t[64 * 64];
__device__ __align__(1024) float g_wb2t[64 * 128];
__device__ __align__(1024) float g_wb3t[128 * 256];

// ---------------------------------------------------------------------------
__device__ __forceinline__ uint32_t cvta_smem(const void* p) {
    return (uint32_t)__cvta_generic_to_shared(p);
}
__device__ __forceinline__ void cpa16(uint32_t dst, const void* src, int sz) {
    asm volatile("cp.async.cg.shared.global [%0], [%1], 16, %2;"
                 :: "r"(dst), "l"(src), "r"(sz) : "memory");
}
__device__ __forceinline__ void cp_commit() {
    asm volatile("cp.async.commit_group;" ::: "memory");
}
#define CP_WAIT1() asm volatile("cp.async.wait_group 1;" ::: "memory")
#define CP_WAIT0() asm volatile("cp.async.wait_group 0;" ::: "memory")
#define LDM4(r, addr)                                                         \
    asm volatile("ldmatrix.sync.aligned.m8n8.x4.shared.b16 "                  \
                 "{%0,%1,%2,%3}, [%4];"                                       \
                 : "=r"((r)[0]), "=r"((r)[1]), "=r"((r)[2]), "=r"((r)[3])     \
                 : "r"(addr))

__device__ __forceinline__ void mma16816(float* d, const uint32_t* a,
                                         uint32_t b0, uint32_t b1) {
    asm volatile(
        "mma.sync.aligned.m16n8k16.row.col.f32.bf16.bf16.f32 "
        "{%0,%1,%2,%3}, {%4,%5,%6,%7}, {%8,%9}, {%0,%1,%2,%3};"
        : "+f"(d[0]), "+f"(d[1]), "+f"(d[2]), "+f"(d[3])
        : "r"(a[0]), "r"(a[1]), "r"(a[2]), "r"(a[3]), "r"(b0), "r"(b1));
}
__device__ __forceinline__ void split2(float v, bf16& h, bf16& l) {
    h = __float2bfloat16(v);
    l = __float2bfloat16(v - __bfloat162float(h));
}
__device__ __forceinline__ uint32_t pack2(bf16 a, bf16 b) {
    return (uint32_t)__bfloat16_as_ushort(a) |
           ((uint32_t)__bfloat16_as_ushort(b) << 16);
}
#define MMA3(acc0, acc1, AH, AL, BH, BL)                                      \
    mma16816(acc0, AH, BH[0], BH[2]); mma16816(acc1, AH, BH[1], BH[3]);       \
    mma16816(acc0, AH, BL[0], BL[2]); mma16816(acc1, AH, BL[1], BL[3]);       \
    mma16816(acc0, AL, BH[0], BH[2]); mma16816(acc1, AL, BH[1], BH[3]);

// ---------------------------------------------------------------------------
// Generalized split-bf16 GEMM. CTA tile 128 x NT, BK=64.
// THREADS threads = WM x WN warps (WN = THREADS/32/WM); warp tile 64 x NT/WN.
// NBUF: 1 = single-buffer (multi-CTA/SM overlap), 2 = double-buffered.
// OUTMODE: 0 = out[m*NS+n]; 2 = z layout out[b*16640 + p*256 + n].
// ---------------------------------------------------------------------------
template<int THREADS, int MINB, int WM, int NBUF,
         int KTOT, int NT, int CIN, int LIN, int LOUT, int STRIDE, int ROFF,
         int OUTMODE, int NS, bool ROWBIAS, bool AF32, bool OUTF32>
__global__ void __launch_bounds__(THREADS, MINB)
gemm_kernel(const float* __restrict__ Af32,
            const bf16* __restrict__ Ahi, const bf16* __restrict__ Alo,
            const bf16* __restrict__ Whi, const bf16* __restrict__ Wlo,
            const float* __restrict__ bias,
            float* __restrict__ Of32, bf16* __restrict__ Ohi,
            bf16* __restrict__ Olo)
{
    constexpr int BK = 64;
    constexpr int NITER = KTOT / BK;
    constexpr int ASZ = 128 * 128;
    constexpr int BSZ = NT * 128;
    constexpr int BUFB = 2 * ASZ + 2 * BSZ;
    constexpr int WN = THREADS / 32 / WM;
    constexpr int NH = NT / WN;
    constexpr int NI = NH / 8;
    constexpr int NL = NH / 16;

    extern __shared__ __align__(1024) char smem_c[];
    const uint32_t smem0 = cvta_smem(smem_c);
    const int tid = threadIdx.x;
    const int lane = tid & 31;
    const int wid = tid >> 5;
    const int warpM = wid / WN, warpN = wid % WN;
    const int n0 = blockIdx.x * NT, m0 = blockIdx.y * 128;

    float acc[4][NI][4];
    #pragma unroll
    for (int mt = 0; mt < 4; ++mt)
        #pragma unroll
        for (int nt = 0; nt < NI; ++nt)
            #pragma unroll
            for (int e = 0; e < 4; ++e) acc[mt][nt][e] = 0.f;

    auto load_tiles = [&](int it, int buf) {
        const int k0 = it * BK;
        const uint32_t sb = smem0 + buf * BUFB;
        #pragma unroll
        for (int v = tid; v < 1024; v += THREADS) {     // A rows x 8 x 16B
            int row = v >> 3, q = v & 7;
            int m = m0 + row;
            int b = m / LOUT, p = m - b * LOUT;
            int k = k0 + q * 8;
            int j = k / CIN, i = k - j * CIN;
            int r = STRIDE * p + j + ROFF;
            bool ok = (r >= 0) && (r < LIN);
            size_t off = (size_t)b * ((size_t)LIN * CIN) + (size_t)r * CIN + i;
            uint32_t so = row * 128 + ((q * 16) ^ ((row & 7) << 4));
            int sz = ok ? 16 : 0;
            cpa16(sb + so, Ahi + off, sz);
            cpa16(sb + ASZ + so, Alo + off, sz);
        }
        #pragma unroll
        for (int v = tid; v < NT * 8; v += THREADS) {   // B
            int n = v >> 3, q = v & 7;
            size_t off = (size_t)(n0 + n) * KTOT + k0 + q * 8;
            uint32_t so = n * 128 + ((q * 16) ^ ((n & 7) << 4));
            cpa16(sb + 2 * ASZ + so, Whi + off, 16);
            cpa16(sb + 2 * ASZ + BSZ + so, Wlo + off, 16);
        }
    };

    if constexpr (AF32) {
        #pragma unroll
        for (int v = tid; v < 2048; v += THREADS) {     // 128 rows x 16 x 8B
            int row = v >> 4, q = v & 15;
            int m = m0 + row;
            int b = m / LOUT, p = m - b * LOUT;
            int i = q * 4;
            int r = p + ROFF;
            bool ok = (r >= 0) && (r < LIN);
            float4 val = ok ? *reinterpret_cast<const float4*>(
                                  Af32 + (size_t)b * ((size_t)LIN * CIN) +
                                  (size_t)r * CIN + i)
                            : make_float4(0.f, 0.f, 0.f, 0.f);
            bf16 h0, h1, h2, h3, l0, l1, l2, l3;
            split2(val.x, h0, l0); split2(val.y, h1, l1);
            split2(val.z, h2, l2); split2(val.w, h3, l3);
            uint32_t so = row * 128 + ((q * 8) ^ ((row & 7) << 4));
            *reinterpret_cast<uint2*>(smem_c + so) =
                make_uint2(pack2(h0, h1), pack2(h2, h3));
            *reinterpret_cast<uint2*>(smem_c + ASZ + so) =
                make_uint2(pack2(l0, l1), pack2(l2, l3));
        }
        #pragma unroll
        for (int v = tid; v < NT * 8; v += THREADS) {
            int n = v >> 3, q = v & 7;
            size_t off = (size_t)(n0 + n) * KTOT + q * 8;
            uint32_t so = n * 128 + ((q * 16) ^ ((n & 7) << 4));
            *reinterpret_cast<uint4*>(smem_c + 2 * ASZ + so) =
                *reinterpret_cast<const uint4*>(Whi + off);
            *reinterpret_cast<uint4*>(smem_c + 2 * ASZ + BSZ + so) =
                *reinterpret_cast<const uint4*>(Wlo + off);
        }
        __syncthreads();
    } else if constexpr (NBUF == 2) {
        load_tiles(0, 0);
        cp_commit();
    }

    const uint32_t aSwz = (uint32_t)(lane & 7) << 4;
    const uint32_t kbBase = (uint32_t)(lane >> 4) << 4;
    uint32_t rowA[4], rowB[NL];
    #pragma unroll
    for (int mt = 0; mt < 4; ++mt)
        rowA[mt] = (uint32_t)(warpM * 64 + mt * 16 + (lane & 15)) * 128;
    #pragma unroll
    for (int c = 0; c < NL; ++c)
        rowB[c] = (uint32_t)(warpN * NH + c * 16 + (lane & 15)) * 128;

    for (int it = 0; it < NITER; ++it) {
        int buf;
        if constexpr (AF32) {
            buf = 0;
        } else if constexpr (NBUF == 1) {
            buf = 0;
            load_tiles(it, 0);
            cp_commit();
            CP_WAIT0();
            __syncthreads();
        } else {
            buf = it & 1;
            if (it + 1 < NITER) {
                load_tiles(it + 1, buf ^ 1);
                cp_commit();
                CP_WAIT1();
            } else {
                CP_WAIT0();
            }
            __syncthreads();
        }

        const uint32_t sAh = smem0 + buf * BUFB;
        const uint32_t sAl = sAh + ASZ;
        const uint32_t sBh = sAl + ASZ;
        const uint32_t sBl = sBh + BSZ;

        #pragma unroll
        for (int ks = 0; ks < 4; ++ks) {
            const uint32_t kb = ((uint32_t)(ks * 32) + kbBase) ^ aSwz;
            uint32_t ah[4][4], al[4][4];
            #pragma unroll
            for (int mt = 0; mt < 4; ++mt) {
                LDM4(ah[mt], sAh + rowA[mt] + kb);
                LDM4(al[mt], sAl + rowA[mt] + kb);
            }
            #pragma unroll
            for (int c = 0; c < NL; ++c) {
                uint32_t bh[4], bl[4];
                LDM4(bh, sBh + rowB[c] + kb);
                LDM4(bl, sBl + rowB[c] + kb);
                #pragma unroll
                for (int mt = 0; mt < 4; ++mt) {
                    MMA3(acc[mt][2 * c], acc[mt][2 * c + 1], ah[mt], al[mt], bh, bl);
                }
            }
        }
        if constexpr (!AF32) {
            if (NBUF == 1 || it + 1 < NITER) __syncthreads();
        }
    }

    const int tr = lane >> 2, tc = (lane & 3) * 2;
    #pragma unroll
    for (int mt = 0; mt < 4; ++mt)
        #pragma unroll
        for (int half = 0; half < 2; ++half) {
            const int m = m0 + warpM * 64 + mt * 16 + tr + half * 8;
            const int bb = m / LOUT;
            const int pp = m - bb * LOUT;
            #pragma unroll
            for (int nt = 0; nt < NI; ++nt) {
                const int n = n0 + warpN * NH + nt * 8 + tc;
                float b0, b1;
                if constexpr (ROWBIAS) {
                    b0 = bias[(size_t)bb * 64 + n];
                    b1 = bias[(size_t)bb * 64 + n + 1];
                } else {
                    b0 = bias[n]; b1 = bias[n + 1];
                }
                const float v0 = fmaxf(acc[mt][nt][half * 2 + 0] + b0, 0.f);
                const float v1 = fmaxf(acc[mt][nt][half * 2 + 1] + b1, 0.f);
                size_t o;
                if constexpr (OUTMODE == 0) o = (size_t)m * NS + n;
                else o = (size_t)bb * 16640 + (size_t)pp * 256 + n;
                if constexpr (OUTF32) {
                    *reinterpret_cast<float2*>(Of32 + o) = make_float2(v0, v1);
                } else {
                    bf16 h0, h1, l0, l1;
                    split2(v0, h0, l0); split2(v1, h1, l1);
                    *reinterpret_cast<uint32_t*>(Ohi + o) = pack2(h0, h1);
                    *reinterpret_cast<uint32_t*>(Olo + o) = pack2(l0, l1);
                }
            }
        }
}

// ---------------------------------------------------------------------------
#define PREP_SA   4096
#define PREP_C1   (128 * 192)
#define PREP_C2   (256 * 384)
#define PREP_C3   (256 * 768)
#define PREP_WPT  4096
#define PREP_WB1  4096
#define PREP_WB2  8192
#define PREP_WB3  32768
#define PREP_SMALL (PREP_SA + PREP_C1 + PREP_C2 + PREP_C3 + PREP_WPT + \
                    PREP_WB1 + PREP_WB2 + PREP_WB3)

__global__ void prep_small_kernel(
    const float* __restrict__ Wp, const float* __restrict__ W1,
    const float* __restrict__ W2, const float* __restrict__ W3,
    const float* __restrict__ Wb1, const float* __restrict__ Wb2,
    const float* __restrict__ Wb3,
    bf16* wah, bf16* wal, bf16* w1h, bf16* w1l, bf16* w2h, bf16* w2l,
    bf16* w3h, bf16* w3l,
    float* wpt, float* wb1t, float* wb2t, float* wb3t)
{
    int idx = blockIdx.x * 256 + threadIdx.x;
    if (idx >= PREP_SMALL) return;
    bf16 h, l;
    if (idx < PREP_SA) {
        int p = idx >> 6, i = idx & 63;
        split2(Wp[p * 128 + i * 2 + 1], h, l);
        wah[idx] = h; wal[idx] = l; return;
    }
    idx -= PREP_SA;
    if (idx < PREP_C1) {
        int o = idx / 192, rem = idx - o * 192;
        int i = rem / 3, j = rem - i * 3;
        split2(W1[idx], h, l);
        w1h[o * 192 + j * 64 + i] = h; w1l[o * 192 + j * 64 + i] = l; return;
    }
    idx -= PREP_C1;
    if (idx < PREP_C2) {
        int o = idx / 384, rem = idx - o * 384;
        int i = rem / 3, j = rem - i * 3;
        split2(W2[idx], h, l);
        w2h[o * 384 + j * 128 + i] = h; w2l[o * 384 + j * 128 + i] = l; return;
    }
    idx -= PREP_C2;
    if (idx < PREP_C3) {
        int o = idx / 768, rem = idx - o * 768;
        int i = rem / 3, j = rem - i * 3;
        split2(W3[idx], h, l);
        w3h[o * 768 + j * 256 + i] = h; w3l[o * 768 + j * 256 + i] = l; return;
    }
    idx -= PREP_C3;
    if (idx < PREP_WPT) { int i = idx >> 6, p = idx & 63; wpt[idx] = Wp[p * 128 + i * 2]; return; }
    idx -= PREP_WPT;
    if (idx < PREP_WB1) { int i = idx >> 6, n = idx & 63; wb1t[idx] = Wb1[n * 64 + i]; return; }
    idx -= PREP_WB1;
    if (idx < PREP_WB2) { int i = idx >> 7, n = idx & 127; wb2t[idx] = Wb2[n * 64 + i]; return; }
    idx -= PREP_WB2;
    { int i = idx >> 8, n = idx & 255; wb3t[idx] = Wb3[n * 128 + i]; }
}

__global__ void __launch_bounds__(256) prep_fc_kernel(
    const float* __restrict__ Wfc1, bf16* __restrict__ wfh,
    bf16* __restrict__ wfl)
{
    extern __shared__ float s[];
    const int n = blockIdx.x, tid = threadIdx.x;
    const float* src = Wfc1 + (size_t)n * 16640;
    for (int k = tid; k < 16384; k += 256) {
        int c = k >> 6, p = k & 63;
        s[c * 65 + p] = src[k];
    }
    __syncthreads();
    bf16* dh = wfh + (size_t)n * 16640;
    bf16* dl = wfl + (size_t)n * 16640;
    for (int k2 = tid; k2 < 16384; k2 += 256) {
        int p = k2 >> 8, c = k2 & 255;
        bf16 h, l;
        split2(s[c * 65 + p], h, l);
        dh[k2] = h; dl[k2] = l;
    }
    for (int k2 = 16384 + tid; k2 < 16640; k2 += 256) {
        bf16 h, l;
        split2(src[k2], h, l);
        dh[k2] = h; dl[k2] = l;
    }
}

#define BB 16
__global__ void __launch_bounds__(256) branch_s0_kernel(
    const float* __restrict__ x,
    const float* __restrict__ wpt,  const float* __restrict__ bp,
    const float* __restrict__ wb1t, const float* __restrict__ bb1,
    const float* __restrict__ wb2t, const float* __restrict__ bb2,
    const float* __restrict__ wb3t, const float* __restrict__ bb3,
    float* __restrict__ s0, bf16* __restrict__ zh, bf16* __restrict__ zl)
{
    __shared__ float x0s[BB][64], f1s[BB][64], f2s[BB][128];
    const int tid = threadIdx.x;
    const int b0 = blockIdx.x * BB;
    #pragma unroll
    for (int t = 0; t < 4; ++t) {
        int idx = tid + t * 256;
        int bs = idx >> 6, i = idx & 63;
        x0s[bs][i] = x[(size_t)(b0 + bs) * 16384 + i];
    }
    __syncthreads();
    #pragma unroll
    for (int t = 0; t < 4; ++t) {
        int idx = tid + t * 256;
        int bs = idx >> 6, n = idx & 63;
        float a0 = bp[n], a1 = bb1[n];
        #pragma unroll 8
        for (int i = 0; i < 64; ++i) {
            float xv = x0s[bs][i];
            a0 += wpt[i * 64 + n] * xv;
            a1 += wb1t[i * 64 + n] * xv;
        }
        s0[(size_t)(b0 + bs) * 64 + n] = a0;
        f1s[bs][n] = fmaxf(a1, 0.f);
    }
    __syncthreads();
    #pragma unroll
    for (int t = 0; t < 8; ++t) {
        int idx = tid + t * 256;
        int bs = idx >> 7, n = idx & 127;
        float a = bb2[n];
        #pragma unroll 8
        for (int i = 0; i < 64; ++i) a += wb2t[i * 128 + n] * f1s[bs][i];
        f2s[bs][n] = fmaxf(a, 0.f);
    }
    __syncthreads();
    #pragma unroll
    for (int t = 0; t < 16; ++t) {
        int idx = tid + t * 256;
        int bs = idx >> 8, n = idx & 255;
        float a = bb3[n];
        #pragma unroll 8
        for (int i = 0; i < 128; ++i) a += wb3t[i * 256 + n] * f2s[bs][i];
        float v = fmaxf(a, 0.f);
        bf16 h, l;
        split2(v, h, l);
        size_t o = (size_t)(b0 + bs) * 16640 + 16384 + n;
        zh[o] = h; zl[o] = l;
    }
}

__global__ void __launch_bounds__(128) fc2_kernel(
    const float* __restrict__ f1, const float* __restrict__ W,
    const float* __restrict__ bias, float* __restrict__ out)
{
    __shared__ float red0[4], red1[4];
    const int b = blockIdx.x, tid = threadIdx.x;
    const float* hb = f1 + (size_t)b * 1024;
    float s0 = 0.f, s1 = 0.f;
    for (int k = tid; k < 1024; k += 128) {
        float v = hb[k];
        s0 += v * W[k];
        s1 += v * W[1024 + k];
    }
    #pragma unroll
    for (int off = 16; off > 0; off >>= 1) {
        s0 += __shfl_down_sync(0xffffffffu, s0, off);
        s1 += __shfl_down_sync(0xffffffffu, s1, off);
    }
    if ((tid & 31) == 0) { red0[tid >> 5] = s0; red1[tid >> 5] = s1; }
    __syncthreads();
    if (tid == 0) {
        out[b * 2 + 0] = red0[0] + red0[1] + red0[2] + red0[3] + bias[0];
        out[b * 2 + 1] = red1[0] + red1[1] + red1[2] + red1[3] + bias[1];
    }
}

// ---------------------------------------------------------------------------
extern "C" void kernel_launch(void* const* d_in, const int* in_sizes, int n_in,
                              void* d_out, int out_size)
{
    const float* x    = (const float*)d_in[0];
    const float* Wp   = (const float*)d_in[1];
    const float* bp   = (const float*)d_in[2];
    const float* W1   = (const float*)d_in[3];
    const float* b1   = (const float*)d_in[4];
    const float* W2   = (const float*)d_in[5];
    const float* b2   = (const float*)d_in[6];
    const float* W3   = (const float*)d_in[7];
    const float* b3   = (const float*)d_in[8];
    const float* Wb1  = (const float*)d_in[9];
    const float* bb1  = (const float*)d_in[10];
    const float* Wb2  = (const float*)d_in[11];
    const float* bb2  = (const float*)d_in[12];
    const float* Wb3  = (const float*)d_in[13];
    const float* bb3  = (const float*)d_in[14];
    const float* Wfc1 = (const float*)d_in[15];
    const float* bfc1 = (const float*)d_in[16];
    const float* Wfc2 = (const float*)d_in[17];
    const float* bfc2 = (const float*)d_in[18];
    float* out = (float*)d_out;

    static void *h0h, *h0l, *h1h, *h1l, *h2h, *h2l, *zh, *zl, *f1, *s0;
    static void *wah, *wal, *w1h, *w1l, *w2h, *w2l, *w3h, *w3l, *wfh, *wfl;
    static void *wpt, *wb1t, *wb2t, *wb3t;
    static bool init = false;
    if (!init) {
        cudaGetSymbolAddress(&h0h, g_h0h); cudaGetSymbolAddress(&h0l, g_h0l);
        cudaGetSymbolAddress(&h1h, g_h1h); cudaGetSymbolAddress(&h1l, g_h1l);
        cudaGetSymbolAddress(&h2h, g_h2h); cudaGetSymbolAddress(&h2l, g_h2l);
        cudaGetSymbolAddress(&zh,  g_zh);  cudaGetSymbolAddress(&zl,  g_zl);
        cudaGetSymbolAddress(&f1,  g_f1);  cudaGetSymbolAddress(&s0,  g_s0);
        cudaGetSymbolAddress(&wah, g_wah); cudaGetSymbolAddress(&wal, g_wal);
        cudaGetSymbolAddress(&w1h, g_w1h); cudaGetSymbolAddress(&w1l, g_w1l);
        cudaGetSymbolAddress(&w2h, g_w2h); cudaGetSymbolAddress(&w2l, g_w2l);
        cudaGetSymbolAddress(&w3h, g_w3h); cudaGetSymbolAddress(&w3l, g_w3l);
        cudaGetSymbolAddress(&wfh, g_wfh); cudaGetSymbolAddress(&wfl, g_wfl);
        cudaGetSymbolAddress(&wpt, g_wpt); cudaGetSymbolAddress(&wb1t, g_wb1t);
        cudaGetSymbolAddress(&wb2t, g_wb2t); cudaGetSymbolAddress(&wb3t, g_wb3t);
        auto setsm = [](const void* f, int bytes) {
            cudaFuncSetAttribute(f, cudaFuncAttributeMaxDynamicSharedMemorySize, bytes);
        };
        setsm((const void*)gemm_kernel<64, 4, 2, 1, 64, 64, 64, 256, 255, 1, 1, 0, 64, true, true, false>, 49152);
        setsm((const void*)gemm_kernel<128, 2, 2, 1, 192, 128, 64, 255, 255, 1, -1, 0, 128, false, false, false>, 65536);
        setsm((const void*)gemm_kernel<256, 1, 2, 2, 384, 256, 128, 255, 128, 2, -1, 0, 256, false, false, false>, 196608);
        setsm((const void*)gemm_kernel<256, 1, 2, 2, 768, 256, 256, 128, 64, 2, -1, 2, 0, false, false, false>, 196608);
        setsm((const void*)gemm_kernel<256, 1, 2, 2, 16640, 128, 16640, 1, 1, 1, 0, 0, 1024, false, false, true>, 131072);
        setsm((const void*)prep_fc_kernel, 256 * 65 * 4);
        init = true;
    }

    prep_small_kernel<<<(PREP_SMALL + 255) / 256, 256>>>(
        Wp, W1, W2, W3, Wb1, Wb2, Wb3,
        (bf16*)wah, (bf16*)wal, (bf16*)w1h, (bf16*)w1l, (bf16*)w2h, (bf16*)w2l,
        (bf16*)w3h, (bf16*)w3l,
        (float*)wpt, (float*)wb1t, (float*)wb2t, (float*)wb3t);
    prep_fc_kernel<<<1024, 256, 256 * 65 * 4>>>(Wfc1, (bf16*)wfh, (bf16*)wfl);

    branch_s0_kernel<<<2048 / BB, 256>>>(
        x, (const float*)wpt, bp, (const float*)wb1t, bb1,
        (const float*)wb2t, bb2, (const float*)wb3t, bb3,
        (float*)s0, (bf16*)zh, (bf16*)zl);

    // stage-A: 64 thr, warp 64x64, 4 CTAs/SM
    gemm_kernel<64, 4, 2, 1, 64, 64, 64, 256, 255, 1, 1, 0, 64, true, true, false>
        <<<dim3(1, 4080), 64, 49152>>>(
            x, nullptr, nullptr, (const bf16*)wah, (const bf16*)wal,
            (const float*)s0, nullptr, (bf16*)h0h, (bf16*)h0l);

    // conv1: 128 thr, warp 64x64, single-buffer, 2 CTAs/SM
    gemm_kernel<128, 2, 2, 1, 192, 128, 64, 255, 255, 1, -1, 0, 128, false, false, false>
        <<<dim3(1, 4080), 128, 65536>>>(
            nullptr, (const bf16*)h0h, (const bf16*)h0l,
            (const bf16*)w1h, (const bf16*)w1l, b1,
            nullptr, (bf16*)h1h, (bf16*)h1l);

    // conv2 (R8 config)
    gemm_kernel<256, 1, 2, 2, 384, 256, 128, 255, 128, 2, -1, 0, 256, false, false, false>
        <<<dim3(1, 2048), 256, 196608>>>(
            nullptr, (const bf16*)h1h, (const bf16*)h1l,
            (const bf16*)w2h, (const bf16*)w2l, b2,
            nullptr, (bf16*)h2h, (bf16*)h2l);

    // conv3 -> z (R8 config)
    gemm_kernel<256, 1, 2, 2, 768, 256, 256, 128, 64, 2, -1, 2, 0, false, false, false>
        <<<dim3(1, 1024), 256, 196608>>>(
            nullptr, (const bf16*)h2h, (const bf16*)h2l,
            (const bf16*)w3h, (const bf16*)w3l, b3,
            nullptr, (bf16*)zh, (bf16*)zl);

    // fc1 (R8 config)
    gemm_kernel<256, 1, 2, 2, 16640, 128, 16640, 1, 1, 1, 0, 0, 1024, false, false, true>
        <<<dim3(8, 16), 256, 131072>>>(
            nullptr, (const bf16*)zh, (const bf16*)zl,
            (const bf16*)wfh, (const bf16*)wfl, bfc1,
            (float*)f1, nullptr, nullptr);

    fc2_kernel<<<2048, 128>>>((const float*)f1, Wfc2, bfc2, out);
}

// round 14
// speedup vs baseline: 1.1072x; 1.0294x over previous
#include <cuda_runtime.h>
#include <cuda_bf16.h>
#include <cstdint>

typedef __nv_bfloat16 bf16;

// ---------------------------------------------------------------------------
__device__ __align__(1024) bf16 g_h0h[(size_t)2048 * 255 * 64];
__device__ __align__(1024) bf16 g_h0l[(size_t)2048 * 255 * 64];
__device__ __align__(1024) bf16 g_h1h[(size_t)2048 * 255 * 128];
__device__ __align__(1024) bf16 g_h1l[(size_t)2048 * 255 * 128];
__device__ __align__(1024) bf16 g_h2h[(size_t)2048 * 128 * 256];
__device__ __align__(1024) bf16 g_h2l[(size_t)2048 * 128 * 256];
__device__ __align__(1024) bf16 g_zh [(size_t)2048 * 16640];
__device__ __align__(1024) bf16 g_zl [(size_t)2048 * 16640];
__device__ __align__(1024) float g_f1p[(size_t)4 * 2048 * 1024];
__device__ __align__(1024) float g_s0[2048 * 64];
__device__ __align__(1024) bf16 g_wah[64 * 64],   g_wal[64 * 64];
__device__ __align__(1024) bf16 g_w1h[128 * 192], g_w1l[128 * 192];
__device__ __align__(1024) bf16 g_w2h[256 * 384], g_w2l[256 * 384];
__device__ __align__(1024) bf16 g_w3h[256 * 768], g_w3l[256 * 768];
__device__ __align__(1024) bf16 g_wfh[(size_t)1024 * 16640];
__device__ __align__(1024) bf16 g_wfl[(size_t)1024 * 16640];
__device__ __align__(1024) float g_wpt [64 * 64];
__device__ __align__(1024) float g_wb1t[64 * 64];
__device__ __align__(1024) float g_wb2t[64 * 128];
__device__ __align__(1024) float g_wb3t[128 * 256];

// ---------------------------------------------------------------------------
__device__ __forceinline__ uint32_t cvta_smem(const void* p) {
    return (uint32_t)__cvta_generic_to_shared(p);
}
__device__ __forceinline__ void cpa16(uint32_t dst, const void* src, int sz) {
    asm volatile("cp.async.cg.shared.global [%0], [%1], 16, %2;"
                 :: "r"(dst), "l"(src), "r"(sz) : "memory");
}
__device__ __forceinline__ void cp_commit() {
    asm volatile("cp.async.commit_group;" ::: "memory");
}
#define CP_WAIT1() asm volatile("cp.async.wait_group 1;" ::: "memory")
#define CP_WAIT0() asm volatile("cp.async.wait_group 0;" ::: "memory")
#define LDM4(r, addr)                                                         \
    asm volatile("ldmatrix.sync.aligned.m8n8.x4.shared.b16 "                  \
                 "{%0,%1,%2,%3}, [%4];"                                       \
                 : "=r"((r)[0]), "=r"((r)[1]), "=r"((r)[2]), "=r"((r)[3])     \
                 : "r"(addr))

__device__ __forceinline__ void mma16816(float* d, const uint32_t* a,
                                         uint32_t b0, uint32_t b1) {
    asm volatile(
        "mma.sync.aligned.m16n8k16.row.col.f32.bf16.bf16.f32 "
        "{%0,%1,%2,%3}, {%4,%5,%6,%7}, {%8,%9}, {%0,%1,%2,%3};"
        : "+f"(d[0]), "+f"(d[1]), "+f"(d[2]), "+f"(d[3])
        : "r"(a[0]), "r"(a[1]), "r"(a[2]), "r"(a[3]), "r"(b0), "r"(b1));
}
__device__ __forceinline__ void split2(float v, bf16& h, bf16& l) {
    h = __float2bfloat16(v);
    l = __float2bfloat16(v - __bfloat162float(h));
}
__device__ __forceinline__ uint32_t pack2(bf16 a, bf16 b) {
    return (uint32_t)__bfloat16_as_ushort(a) |
           ((uint32_t)__bfloat16_as_ushort(b) << 16);
}
#define MMA3(acc0, acc1, AH, AL, BH, BL)                                      \
    mma16816(acc0, AH, BH[0], BH[2]); mma16816(acc1, AH, BH[1], BH[3]);       \
    mma16816(acc0, AH, BL[0], BL[2]); mma16816(acc1, AH, BL[1], BL[3]);       \
    mma16816(acc0, AL, BH[0], BH[2]); mma16816(acc1, AL, BH[1], BH[3]);

// ---------------------------------------------------------------------------
// Generalized split-bf16 GEMM. CTA tile 128 x NT, BK=64, k-split via gridDim.z
// (KTOT = iterated K per split; KFULL = row stride in memory).
// THREADS = WM x WN warps; warp tile 64 x NT/WN. NBUF 1|2.
// OUTMODE: 0 = out[m*NS+n] (+bias,relu); 2 = z layout; 3 = fp32 partial.
// ---------------------------------------------------------------------------
template<int THREADS, int MINB, int WM, int NBUF,
         int KTOT, int KFULL, int NT, int CIN, int LIN, int LOUT, int STRIDE,
         int ROFF, int OUTMODE, int NS, bool ROWBIAS, bool AF32, bool OUTF32>
__global__ void __launch_bounds__(THREADS, MINB)
gemm_kernel(const float* __restrict__ Af32,
            const bf16* __restrict__ Ahi, const bf16* __restrict__ Alo,
            const bf16* __restrict__ Whi, const bf16* __restrict__ Wlo,
            const float* __restrict__ bias,
            float* __restrict__ Of32, bf16* __restrict__ Ohi,
            bf16* __restrict__ Olo)
{
    constexpr int BK = 64;
    constexpr int NITER = KTOT / BK;
    constexpr int ASZ = 128 * 128;
    constexpr int BSZ = NT * 128;
    constexpr int BUFB = 2 * ASZ + 2 * BSZ;
    constexpr int WN = THREADS / 32 / WM;
    constexpr int NH = NT / WN;
    constexpr int NI = NH / 8;
    constexpr int NL = NH / 16;

    extern __shared__ __align__(1024) char smem_c[];
    const uint32_t smem0 = cvta_smem(smem_c);
    const int tid = threadIdx.x;
    const int lane = tid & 31;
    const int wid = tid >> 5;
    const int warpM = wid / WN, warpN = wid % WN;
    const int n0 = blockIdx.x * NT, m0 = blockIdx.y * 128;
    const int kb0 = blockIdx.z * KTOT;

    float acc[4][NI][4];
    #pragma unroll
    for (int mt = 0; mt < 4; ++mt)
        #pragma unroll
        for (int nt = 0; nt < NI; ++nt)
            #pragma unroll
            for (int e = 0; e < 4; ++e) acc[mt][nt][e] = 0.f;

    auto load_tiles = [&](int it, int buf) {
        const int k0 = it * BK;
        const uint32_t sb = smem0 + buf * BUFB;
        #pragma unroll
        for (int v = tid; v < 1024; v += THREADS) {
            int row = v >> 3, q = v & 7;
            int m = m0 + row;
            int b = m / LOUT, p = m - b * LOUT;
            int k = k0 + q * 8;
            int j = k / CIN, i = k - j * CIN;
            int r = STRIDE * p + j + ROFF;
            bool ok = (r >= 0) && (r < LIN);
            size_t off = (size_t)b * ((size_t)LIN * CIN) + (size_t)r * CIN + i + kb0;
            uint32_t so = row * 128 + ((q * 16) ^ ((row & 7) << 4));
            int sz = ok ? 16 : 0;
            cpa16(sb + so, Ahi + off, sz);
            cpa16(sb + ASZ + so, Alo + off, sz);
        }
        #pragma unroll
        for (int v = tid; v < NT * 8; v += THREADS) {
            int n = v >> 3, q = v & 7;
            size_t off = (size_t)(n0 + n) * KFULL + kb0 + k0 + q * 8;
            uint32_t so = n * 128 + ((q * 16) ^ ((n & 7) << 4));
            cpa16(sb + 2 * ASZ + so, Whi + off, 16);
            cpa16(sb + 2 * ASZ + BSZ + so, Wlo + off, 16);
        }
    };

    if constexpr (AF32) {
        #pragma unroll
        for (int v = tid; v < 2048; v += THREADS) {
            int row = v >> 4, q = v & 15;
            int m = m0 + row;
            int b = m / LOUT, p = m - b * LOUT;
            int i = q * 4;
            int r = p + ROFF;
            bool ok = (r >= 0) && (r < LIN);
            float4 val = ok ? *reinterpret_cast<const float4*>(
                                  Af32 + (size_t)b * ((size_t)LIN * CIN) +
                                  (size_t)r * CIN + i)
                            : make_float4(0.f, 0.f, 0.f, 0.f);
            bf16 h0, h1, h2, h3, l0, l1, l2, l3;
            split2(val.x, h0, l0); split2(val.y, h1, l1);
            split2(val.z, h2, l2); split2(val.w, h3, l3);
            uint32_t so = row * 128 + ((q * 8) ^ ((row & 7) << 4));
            *reinterpret_cast<uint2*>(smem_c + so) =
                make_uint2(pack2(h0, h1), pack2(h2, h3));
            *reinterpret_cast<uint2*>(smem_c + ASZ + so) =
                make_uint2(pack2(l0, l1), pack2(l2, l3));
        }
        #pragma unroll
        for (int v = tid; v < NT * 8; v += THREADS) {
            int n = v >> 3, q = v & 7;
            size_t off = (size_t)(n0 + n) * KFULL + q * 8;
            uint32_t so = n * 128 + ((q * 16) ^ ((n & 7) << 4));
            *reinterpret_cast<uint4*>(smem_c + 2 * ASZ + so) =
                *reinterpret_cast<const uint4*>(Whi + off);
            *reinterpret_cast<uint4*>(smem_c + 2 * ASZ + BSZ + so) =
                *reinterpret_cast<const uint4*>(Wlo + off);
        }
        __syncthreads();
    } else if constexpr (NBUF == 2) {
        load_tiles(0, 0);
        cp_commit();
    }

    const uint32_t aSwz = (uint32_t)(lane & 7) << 4;
    const uint32_t kbBase = (uint32_t)(lane >> 4) << 4;
    uint32_t rowA[4], rowB[NL];
    #pragma unroll
    for (int mt = 0; mt < 4; ++mt)
        rowA[mt] = (uint32_t)(warpM * 64 + mt * 16 + (lane & 15)) * 128;
    #pragma unroll
    for (int c = 0; c < NL; ++c)
        rowB[c] = (uint32_t)(warpN * NH + c * 16 + (lane & 15)) * 128;

    for (int it = 0; it < NITER; ++it) {
        int buf;
        if constexpr (AF32) {
            buf = 0;
        } else if constexpr (NBUF == 1) {
            buf = 0;
            load_tiles(it, 0);
            cp_commit();
            CP_WAIT0();
            __syncthreads();
        } else {
            buf = it & 1;
            if (it + 1 < NITER) {
                load_tiles(it + 1, buf ^ 1);
                cp_commit();
                CP_WAIT1();
            } else {
                CP_WAIT0();
            }
            __syncthreads();
        }

        const uint32_t sAh = smem0 + buf * BUFB;
        const uint32_t sAl = sAh + ASZ;
        const uint32_t sBh = sAl + ASZ;
        const uint32_t sBl = sBh + BSZ;

        #pragma unroll
        for (int ks = 0; ks < 4; ++ks) {
            const uint32_t kb = ((uint32_t)(ks * 32) + kbBase) ^ aSwz;
            uint32_t ah[4][4], al[4][4];
            #pragma unroll
            for (int mt = 0; mt < 4; ++mt) {
                LDM4(ah[mt], sAh + rowA[mt] + kb);
                LDM4(al[mt], sAl + rowA[mt] + kb);
            }
            #pragma unroll
            for (int c = 0; c < NL; ++c) {
                uint32_t bh[4], bl[4];
                LDM4(bh, sBh + rowB[c] + kb);
                LDM4(bl, sBl + rowB[c] + kb);
                #pragma unroll
                for (int mt = 0; mt < 4; ++mt) {
                    MMA3(acc[mt][2 * c], acc[mt][2 * c + 1], ah[mt], al[mt], bh, bl);
                }
            }
        }
        if constexpr (!AF32) {
            if (NBUF == 1 || it + 1 < NITER) __syncthreads();
        }
    }

    const int tr = lane >> 2, tc = (lane & 3) * 2;
    #pragma unroll
    for (int mt = 0; mt < 4; ++mt)
        #pragma unroll
        for (int half = 0; half < 2; ++half) {
            const int m = m0 + warpM * 64 + mt * 16 + tr + half * 8;
            const int bb = m / LOUT;
            const int pp = m - bb * LOUT;
            #pragma unroll
            for (int nt = 0; nt < NI; ++nt) {
                const int n = n0 + warpN * NH + nt * 8 + tc;
                const float d0 = acc[mt][nt][half * 2 + 0];
                const float d1 = acc[mt][nt][half * 2 + 1];
                if constexpr (OUTMODE == 3) {
                    size_t o = (size_t)blockIdx.z * (2048 * 1024) +
                               (size_t)m * NS + n;
                    *reinterpret_cast<float2*>(Of32 + o) = make_float2(d0, d1);
                    continue;
                }
                float b0, b1;
                if constexpr (ROWBIAS) {
                    b0 = bias[(size_t)bb * 64 + n];
                    b1 = bias[(size_t)bb * 64 + n + 1];
                } else {
                    b0 = bias[n]; b1 = bias[n + 1];
                }
                const float v0 = fmaxf(d0 + b0, 0.f);
                const float v1 = fmaxf(d1 + b1, 0.f);
                size_t o;
                if constexpr (OUTMODE == 0) o = (size_t)m * NS + n;
                else o = (size_t)bb * 16640 + (size_t)pp * 256 + n;
                if constexpr (OUTF32) {
                    *reinterpret_cast<float2*>(Of32 + o) = make_float2(v0, v1);
                } else {
                    bf16 h0, h1, l0, l1;
                    split2(v0, h0, l0); split2(v1, h1, l1);
                    *reinterpret_cast<uint32_t*>(Ohi + o) = pack2(h0, h1);
                    *reinterpret_cast<uint32_t*>(Olo + o) = pack2(l0, l1);
                }
            }
        }
}

// ---------------------------------------------------------------------------
#define PREP_SA   4096
#define PREP_C1   (128 * 192)
#define PREP_C2   (256 * 384)
#define PREP_C3   (256 * 768)
#define PREP_WPT  4096
#define PREP_WB1  4096
#define PREP_WB2  8192
#define PREP_WB3  32768
#define PREP_SMALL (PREP_SA + PREP_C1 + PREP_C2 + PREP_C3 + PREP_WPT + \
                    PREP_WB1 + PREP_WB2 + PREP_WB3)

__global__ void prep_small_kernel(
    const float* __restrict__ Wp, const float* __restrict__ W1,
    const float* __restrict__ W2, const float* __restrict__ W3,
    const float* __restrict__ Wb1, const float* __restrict__ Wb2,
    const float* __restrict__ Wb3,
    bf16* wah, bf16* wal, bf16* w1h, bf16* w1l, bf16* w2h, bf16* w2l,
    bf16* w3h, bf16* w3l,
    float* wpt, float* wb1t, float* wb2t, float* wb3t)
{
    int idx = blockIdx.x * 256 + threadIdx.x;
    if (idx >= PREP_SMALL) return;
    bf16 h, l;
    if (idx < PREP_SA) {
        int p = idx >> 6, i = idx & 63;
        split2(Wp[p * 128 + i * 2 + 1], h, l);
        wah[idx] = h; wal[idx] = l; return;
    }
    idx -= PREP_SA;
    if (idx < PREP_C1) {
        int o = idx / 192, rem = idx - o * 192;
        int i = rem / 3, j = rem - i * 3;
        split2(W1[idx], h, l);
        w1h[o * 192 + j * 64 + i] = h; w1l[o * 192 + j * 64 + i] = l; return;
    }
    idx -= PREP_C1;
    if (idx < PREP_C2) {
        int o = idx / 384, rem = idx - o * 384;
        int i = rem / 3, j = rem - i * 3;
        split2(W2[idx], h, l);
        w2h[o * 384 + j * 128 + i] = h; w2l[o * 384 + j * 128 + i] = l; return;
    }
    idx -= PREP_C2;
    if (idx < PREP_C3) {
        int o = idx / 768, rem = idx - o * 768;
        int i = rem / 3, j = rem - i * 3;
        split2(W3[idx], h, l);
        w3h[o * 768 + j * 256 + i] = h; w3l[o * 768 + j * 256 + i] = l; return;
    }
    idx -= PREP_C3;
    if (idx < PREP_WPT) { int i = idx >> 6, p = idx & 63; wpt[idx] = Wp[p * 128 + i * 2]; return; }
    idx -= PREP_WPT;
    if (idx < PREP_WB1) { int i = idx >> 6, n = idx & 63; wb1t[idx] = Wb1[n * 64 + i]; return; }
    idx -= PREP_WB1;
    if (idx < PREP_WB2) { int i = idx >> 7, n = idx & 127; wb2t[idx] = Wb2[n * 64 + i]; return; }
    idx -= PREP_WB2;
    { int i = idx >> 8, n = idx & 255; wb3t[idx] = Wb3[n * 128 + i]; }
}

__global__ void __launch_bounds__(256) prep_fc_kernel(
    const float* __restrict__ Wfc1, bf16* __restrict__ wfh,
    bf16* __restrict__ wfl)
{
    extern __shared__ float s[];
    const int n = blockIdx.x, tid = threadIdx.x;
    const float* src = Wfc1 + (size_t)n * 16640;
    for (int k = tid; k < 16384; k += 256) {
        int c = k >> 6, p = k & 63;
        s[c * 65 + p] = src[k];
    }
    __syncthreads();
    bf16* dh = wfh + (size_t)n * 16640;
    bf16* dl = wfl + (size_t)n * 16640;
    for (int k2 = tid; k2 < 16384; k2 += 256) {
        int p = k2 >> 8, c = k2 & 255;
        bf16 h, l;
        split2(s[c * 65 + p], h, l);
        dh[k2] = h; dl[k2] = l;
    }
    for (int k2 = 16384 + tid; k2 < 16640; k2 += 256) {
        bf16 h, l;
        split2(src[k2], h, l);
        dh[k2] = h; dl[k2] = l;
    }
}

#define BB 16
__global__ void __launch_bounds__(256) branch_s0_kernel(
    const float* __restrict__ x,
    const float* __restrict__ wpt,  const float* __restrict__ bp,
    const float* __restrict__ wb1t, const float* __restrict__ bb1,
    const float* __restrict__ wb2t, const float* __restrict__ bb2,
    const float* __restrict__ wb3t, const float* __restrict__ bb3,
    float* __restrict__ s0, bf16* __restrict__ zh, bf16* __restrict__ zl)
{
    __shared__ float x0s[BB][64], f1s[BB][64], f2s[BB][128];
    const int tid = threadIdx.x;
    const int b0 = blockIdx.x * BB;
    #pragma unroll
    for (int t = 0; t < 4; ++t) {
        int idx = tid + t * 256;
        int bs = idx >> 6, i = idx & 63;
        x0s[bs][i] = x[(size_t)(b0 + bs) * 16384 + i];
    }
    __syncthreads();
    #pragma unroll
    for (int t = 0; t < 4; ++t) {
        int idx = tid + t * 256;
        int bs = idx >> 6, n = idx & 63;
        float a0 = bp[n], a1 = bb1[n];
        #pragma unroll 8
        for (int i = 0; i < 64; ++i) {
            float xv = x0s[bs][i];
            a0 += wpt[i * 64 + n] * xv;
            a1 += wb1t[i * 64 + n] * xv;
        }
        s0[(size_t)(b0 + bs) * 64 + n] = a0;
        f1s[bs][n] = fmaxf(a1, 0.f);
    }
    __syncthreads();
    #pragma unroll
    for (int t = 0; t < 8; ++t) {
        int idx = tid + t * 256;
        int bs = idx >> 7, n = idx & 127;
        float a = bb2[n];
        #pragma unroll 8
        for (int i = 0; i < 64; ++i) a += wb2t[i * 128 + n] * f1s[bs][i];
        f2s[bs][n] = fmaxf(a, 0.f);
    }
    __syncthreads();
    #pragma unroll
    for (int t = 0; t < 16; ++t) {
        int idx = tid + t * 256;
        int bs = idx >> 8, n = idx & 255;
        float a = bb3[n];
        #pragma unroll 8
        for (int i = 0; i < 128; ++i) a += wb3t[i * 256 + n] * f2s[bs][i];
        float v = fmaxf(a, 0.f);
        bf16 h, l;
        split2(v, h, l);
        size_t o = (size_t)(b0 + bs) * 16640 + 16384 + n;
        zh[o] = h; zl[o] = l;
    }
}

// fc2: sums 4 fc1 partials + bias + relu, then the 1024->2 dot.
__global__ void __launch_bounds__(128) fc2_kernel(
    const float* __restrict__ f1p, const float* __restrict__ bfc1,
    const float* __restrict__ W, const float* __restrict__ bias,
    float* __restrict__ out)
{
    __shared__ float red0[4], red1[4];
    const int b = blockIdx.x, tid = threadIdx.x;
    const float* p0 = f1p + (size_t)b * 1024;
    float s0 = 0.f, s1 = 0.f;
    for (int k = tid; k < 1024; k += 128) {
        float v = p0[k] + p0[(size_t)2048 * 1024 + k] +
                  p0[(size_t)2 * 2048 * 1024 + k] +
                  p0[(size_t)3 * 2048 * 1024 + k] + bfc1[k];
        v = fmaxf(v, 0.f);
        s0 += v * W[k];
        s1 += v * W[1024 + k];
    }
    #pragma unroll
    for (int off = 16; off > 0; off >>= 1) {
        s0 += __shfl_down_sync(0xffffffffu, s0, off);
        s1 += __shfl_down_sync(0xffffffffu, s1, off);
    }
    if ((tid & 31) == 0) { red0[tid >> 5] = s0; red1[tid >> 5] = s1; }
    __syncthreads();
    if (tid == 0) {
        out[b * 2 + 0] = red0[0] + red0[1] + red0[2] + red0[3] + bias[0];
        out[b * 2 + 1] = red1[0] + red1[1] + red1[2] + red1[3] + bias[1];
    }
}

// ---------------------------------------------------------------------------
extern "C" void kernel_launch(void* const* d_in, const int* in_sizes, int n_in,
                              void* d_out, int out_size)
{
    const float* x    = (const float*)d_in[0];
    const float* Wp   = (const float*)d_in[1];
    const float* bp   = (const float*)d_in[2];
    const float* W1   = (const float*)d_in[3];
    const float* b1   = (const float*)d_in[4];
    const float* W2   = (const float*)d_in[5];
    const float* b2   = (const float*)d_in[6];
    const float* W3   = (const float*)d_in[7];
    const float* b3   = (const float*)d_in[8];
    const float* Wb1  = (const float*)d_in[9];
    const float* bb1  = (const float*)d_in[10];
    const float* Wb2  = (const float*)d_in[11];
    const float* bb2  = (const float*)d_in[12];
    const float* Wb3  = (const float*)d_in[13];
    const float* bb3  = (const float*)d_in[14];
    const float* Wfc1 = (const float*)d_in[15];
    const float* bfc1 = (const float*)d_in[16];
    const float* Wfc2 = (const float*)d_in[17];
    const float* bfc2 = (const float*)d_in[18];
    float* out = (float*)d_out;

    static void *h0h, *h0l, *h1h, *h1l, *h2h, *h2l, *zh, *zl, *f1p, *s0;
    static void *wah, *wal, *w1h, *w1l, *w2h, *w2l, *w3h, *w3l, *wfh, *wfl;
    static void *wpt, *wb1t, *wb2t, *wb3t;
    static bool init = false;
    if (!init) {
        cudaGetSymbolAddress(&h0h, g_h0h); cudaGetSymbolAddress(&h0l, g_h0l);
        cudaGetSymbolAddress(&h1h, g_h1h); cudaGetSymbolAddress(&h1l, g_h1l);
        cudaGetSymbolAddress(&h2h, g_h2h); cudaGetSymbolAddress(&h2l, g_h2l);
        cudaGetSymbolAddress(&zh,  g_zh);  cudaGetSymbolAddress(&zl,  g_zl);
        cudaGetSymbolAddress(&f1p, g_f1p); cudaGetSymbolAddress(&s0,  g_s0);
        cudaGetSymbolAddress(&wah, g_wah); cudaGetSymbolAddress(&wal, g_wal);
        cudaGetSymbolAddress(&w1h, g_w1h); cudaGetSymbolAddress(&w1l, g_w1l);
        cudaGetSymbolAddress(&w2h, g_w2h); cudaGetSymbolAddress(&w2l, g_w2l);
        cudaGetSymbolAddress(&w3h, g_w3h); cudaGetSymbolAddress(&w3l, g_w3l);
        cudaGetSymbolAddress(&wfh, g_wfh); cudaGetSymbolAddress(&wfl, g_wfl);
        cudaGetSymbolAddress(&wpt, g_wpt); cudaGetSymbolAddress(&wb1t, g_wb1t);
        cudaGetSymbolAddress(&wb2t, g_wb2t); cudaGetSymbolAddress(&wb3t, g_wb3t);
        auto setsm = [](const void* f, int bytes) {
            cudaFuncSetAttribute(f, cudaFuncAttributeMaxDynamicSharedMemorySize, bytes);
        };
        setsm((const void*)gemm_kernel<64, 4, 2, 1, 64, 64, 64, 64, 256, 255, 1, 1, 0, 64, true, true, false>, 49152);
        setsm((const void*)gemm_kernel<128, 2, 2, 1, 192, 192, 128, 64, 255, 255, 1, -1, 0, 128, false, false, false>, 65536);
        setsm((const void*)gemm_kernel<256, 1, 2, 2, 384, 384, 256, 128, 255, 128, 2, -1, 0, 256, false, false, false>, 196608);
        setsm((const void*)gemm_kernel<256, 1, 2, 2, 768, 768, 256, 256, 128, 64, 2, -1, 2, 0, false, false, false>, 196608);
        setsm((const void*)gemm_kernel<256, 1, 2, 2, 4160, 16640, 256, 16640, 1, 1, 1, 0, 3, 1024, false, false, true>, 196608);
        setsm((const void*)prep_fc_kernel, 256 * 65 * 4);
        init = true;
    }

    prep_small_kernel<<<(PREP_SMALL + 255) / 256, 256>>>(
        Wp, W1, W2, W3, Wb1, Wb2, Wb3,
        (bf16*)wah, (bf16*)wal, (bf16*)w1h, (bf16*)w1l, (bf16*)w2h, (bf16*)w2l,
        (bf16*)w3h, (bf16*)w3l,
        (float*)wpt, (float*)wb1t, (float*)wb2t, (float*)wb3t);
    prep_fc_kernel<<<1024, 256, 256 * 65 * 4>>>(Wfc1, (bf16*)wfh, (bf16*)wfl);

    branch_s0_kernel<<<2048 / BB, 256>>>(
        x, (const float*)wpt, bp, (const float*)wb1t, bb1,
        (const float*)wb2t, bb2, (const float*)wb3t, bb3,
        (float*)s0, (bf16*)zh, (bf16*)zl);

    // stage-A (R13 config)
    gemm_kernel<64, 4, 2, 1, 64, 64, 64, 64, 256, 255, 1, 1, 0, 64, true, true, false>
        <<<dim3(1, 4080), 64, 49152>>>(
            x, nullptr, nullptr, (const bf16*)wah, (const bf16*)wal,
            (const float*)s0, nullptr, (bf16*)h0h, (bf16*)h0l);

    // conv1 (R13 config)
    gemm_kernel<128, 2, 2, 1, 192, 192, 128, 64, 255, 255, 1, -1, 0, 128, false, false, false>
        <<<dim3(1, 4080), 128, 65536>>>(
            nullptr, (const bf16*)h0h, (const bf16*)h0l,
            (const bf16*)w1h, (const bf16*)w1l, b1,
            nullptr, (bf16*)h1h, (bf16*)h1l);

    // conv2 (R8 config)
    gemm_kernel<256, 1, 2, 2, 384, 384, 256, 128, 255, 128, 2, -1, 0, 256, false, false, false>
        <<<dim3(1, 2048), 256, 196608>>>(
            nullptr, (const bf16*)h1h, (const bf16*)h1l,
            (const bf16*)w2h, (const bf16*)w2l, b2,
            nullptr, (bf16*)h2h, (bf16*)h2l);

    // conv3 -> z (R8 config)
    gemm_kernel<256, 1, 2, 2, 768, 768, 256, 256, 128, 64, 2, -1, 2, 0, false, false, false>
        <<<dim3(1, 1024), 256, 196608>>>(
            nullptr, (const bf16*)h2h, (const bf16*)h2l,
            (const bf16*)w3h, (const bf16*)w3l, b3,
            nullptr, (bf16*)zh, (bf16*)zl);

    // fc1: conv2-shaped (warp 64x64), 4-way k-split -> fp32 partials
    gemm_kernel<256, 1, 2, 2, 4160, 16640, 256, 16640, 1, 1, 1, 0, 3, 1024, false, false, true>
        <<<dim3(4, 16, 4), 256, 196608>>>(
            nullptr, (const bf16*)zh, (const bf16*)zl,
            (const bf16*)wfh, (const bf16*)wfl, nullptr,
            (float*)f1p, nullptr, nullptr);

    fc2_kernel<<<2048, 128>>>((const float*)f1p, bfc1, Wfc2, bfc2, out);
}

// round 15
// speedup vs baseline: 1.1103x; 1.0028x over previous
#include <cuda_runtime.h>
#include <cuda_bf16.h>
#include <cstdint>

typedef __nv_bfloat16 bf16;

// ---------------------------------------------------------------------------
__device__ __align__(1024) bf16 g_h0h[(size_t)2048 * 255 * 64];
__device__ __align__(1024) bf16 g_h0l[(size_t)2048 * 255 * 64];
__device__ __align__(1024) bf16 g_h1h[(size_t)2048 * 255 * 128];
__device__ __align__(1024) bf16 g_h1l[(size_t)2048 * 255 * 128];
__device__ __align__(1024) bf16 g_h2h[(size_t)2048 * 128 * 256];
__device__ __align__(1024) bf16 g_h2l[(size_t)2048 * 128 * 256];
__device__ __align__(1024) bf16 g_zh [(size_t)2048 * 16640];
__device__ __align__(1024) bf16 g_zl [(size_t)2048 * 16640];
__device__ __align__(1024) float g_f1p[(size_t)4 * 2048 * 1024];
__device__ __align__(1024) float g_s0[2048 * 64];
__device__ __align__(1024) bf16 g_wah[64 * 64],   g_wal[64 * 64];
__device__ __align__(1024) bf16 g_w1h[128 * 192], g_w1l[128 * 192];
__device__ __align__(1024) bf16 g_w2h[256 * 384], g_w2l[256 * 384];
__device__ __align__(1024) bf16 g_w3h[256 * 768], g_w3l[256 * 768];
__device__ __align__(1024) bf16 g_wfh[(size_t)1024 * 16640];
__device__ __align__(1024) bf16 g_wfl[(size_t)1024 * 16640];
__device__ __align__(1024) float g_wpt [64 * 64];
__device__ __align__(1024) float g_wb1t[64 * 64];
__device__ __align__(1024) float g_wb2t[64 * 128];
__device__ __align__(1024) float g_wb3t[128 * 256];

// ---------------------------------------------------------------------------
__device__ __forceinline__ uint32_t cvta_smem(const void* p) {
    return (uint32_t)__cvta_generic_to_shared(p);
}
__device__ __forceinline__ void cpa16(uint32_t dst, const void* src, int sz) {
    asm volatile("cp.async.cg.shared.global [%0], [%1], 16, %2;"
                 :: "r"(dst), "l"(src), "r"(sz) : "memory");
}
__device__ __forceinline__ void cp_commit() {
    asm volatile("cp.async.commit_group;" ::: "memory");
}
#define CP_WAIT1() asm volatile("cp.async.wait_group 1;" ::: "memory")
#define CP_WAIT0() asm volatile("cp.async.wait_group 0;" ::: "memory")
#define LDM4(r, addr)                                                         \
    asm volatile("ldmatrix.sync.aligned.m8n8.x4.shared.b16 "                  \
                 "{%0,%1,%2,%3}, [%4];"                                       \
                 : "=r"((r)[0]), "=r"((r)[1]), "=r"((r)[2]), "=r"((r)[3])     \
                 : "r"(addr))

__device__ __forceinline__ void mma16816(float* d, const uint32_t* a,
                                         uint32_t b0, uint32_t b1) {
    asm volatile(
        "mma.sync.aligned.m16n8k16.row.col.f32.bf16.bf16.f32 "
        "{%0,%1,%2,%3}, {%4,%5,%6,%7}, {%8,%9}, {%0,%1,%2,%3};"
        : "+f"(d[0]), "+f"(d[1]), "+f"(d[2]), "+f"(d[3])
        : "r"(a[0]), "r"(a[1]), "r"(a[2]), "r"(a[3]), "r"(b0), "r"(b1));
}
__device__ __forceinline__ void split2(float v, bf16& h, bf16& l) {
    h = __float2bfloat16(v);
    l = __float2bfloat16(v - __bfloat162float(h));
}
__device__ __forceinline__ uint32_t pack2(bf16 a, bf16 b) {
    return (uint32_t)__bfloat16_as_ushort(a) |
           ((uint32_t)__bfloat16_as_ushort(b) << 16);
}
#define MMA3(acc0, acc1, AH, AL, BH, BL)                                      \
    mma16816(acc0, AH, BH[0], BH[2]); mma16816(acc1, AH, BH[1], BH[3]);       \
    mma16816(acc0, AH, BL[0], BL[2]); mma16816(acc1, AH, BL[1], BL[3]);       \
    mma16816(acc0, AL, BH[0], BH[2]); mma16816(acc1, AL, BH[1], BH[3]);

// ---------------------------------------------------------------------------
// Generalized split-bf16 GEMM. CTA tile 128 x NT, BK=64, k-split via gridDim.z
// (KTOT = iterated K per split; KFULL = row stride in memory).
// THREADS = WM x WN warps; warp tile 64 x NT/WN. NBUF 1|2.
// OUTMODE: 0 = out[m*NS+n] (+bias,relu); 2 = z layout; 3 = fp32 partial.
// ---------------------------------------------------------------------------
template<int THREADS, int MINB, int WM, int NBUF,
         int KTOT, int KFULL, int NT, int CIN, int LIN, int LOUT, int STRIDE,
         int ROFF, int OUTMODE, int NS, bool ROWBIAS, bool AF32, bool OUTF32>
__global__ void __launch_bounds__(THREADS, MINB)
gemm_kernel(const float* __restrict__ Af32,
            const bf16* __restrict__ Ahi, const bf16* __restrict__ Alo,
            const bf16* __restrict__ Whi, const bf16* __restrict__ Wlo,
            const float* __restrict__ bias,
            float* __restrict__ Of32, bf16* __restrict__ Ohi,
            bf16* __restrict__ Olo)
{
    constexpr int BK = 64;
    constexpr int NITER = KTOT / BK;
    constexpr int ASZ = 128 * 128;
    constexpr int BSZ = NT * 128;
    constexpr int BUFB = 2 * ASZ + 2 * BSZ;
    constexpr int WN = THREADS / 32 / WM;
    constexpr int NH = NT / WN;
    constexpr int NI = NH / 8;
    constexpr int NL = NH / 16;

    extern __shared__ __align__(1024) char smem_c[];
    const uint32_t smem0 = cvta_smem(smem_c);
    const int tid = threadIdx.x;
    const int lane = tid & 31;
    const int wid = tid >> 5;
    const int warpM = wid / WN, warpN = wid % WN;
    const int n0 = blockIdx.x * NT, m0 = blockIdx.y * 128;
    const int kb0 = blockIdx.z * KTOT;

    float acc[4][NI][4];
    #pragma unroll
    for (int mt = 0; mt < 4; ++mt)
        #pragma unroll
        for (int nt = 0; nt < NI; ++nt)
            #pragma unroll
            for (int e = 0; e < 4; ++e) acc[mt][nt][e] = 0.f;

    auto load_tiles = [&](int it, int buf) {
        const int k0 = it * BK;
        const uint32_t sb = smem0 + buf * BUFB;
        #pragma unroll
        for (int v = tid; v < 1024; v += THREADS) {
            int row = v >> 3, q = v & 7;
            int m = m0 + row;
            int b = m / LOUT, p = m - b * LOUT;
            int k = k0 + q * 8;
            int j = k / CIN, i = k - j * CIN;
            int r = STRIDE * p + j + ROFF;
            bool ok = (r >= 0) && (r < LIN);
            size_t off = (size_t)b * ((size_t)LIN * CIN) + (size_t)r * CIN + i + kb0;
            uint32_t so = row * 128 + ((q * 16) ^ ((row & 7) << 4));
            int sz = ok ? 16 : 0;
            cpa16(sb + so, Ahi + off, sz);
            cpa16(sb + ASZ + so, Alo + off, sz);
        }
        #pragma unroll
        for (int v = tid; v < NT * 8; v += THREADS) {
            int n = v >> 3, q = v & 7;
            size_t off = (size_t)(n0 + n) * KFULL + kb0 + k0 + q * 8;
            uint32_t so = n * 128 + ((q * 16) ^ ((n & 7) << 4));
            cpa16(sb + 2 * ASZ + so, Whi + off, 16);
            cpa16(sb + 2 * ASZ + BSZ + so, Wlo + off, 16);
        }
    };

    if constexpr (AF32) {
        #pragma unroll
        for (int v = tid; v < 2048; v += THREADS) {
            int row = v >> 4, q = v & 15;
            int m = m0 + row;
            int b = m / LOUT, p = m - b * LOUT;
            int i = q * 4;
            int r = p + ROFF;
            bool ok = (r >= 0) && (r < LIN);
            float4 val = ok ? *reinterpret_cast<const float4*>(
                                  Af32 + (size_t)b * ((size_t)LIN * CIN) +
                                  (size_t)r * CIN + i)
                            : make_float4(0.f, 0.f, 0.f, 0.f);
            bf16 h0, h1, h2, h3, l0, l1, l2, l3;
            split2(val.x, h0, l0); split2(val.y, h1, l1);
            split2(val.z, h2, l2); split2(val.w, h3, l3);
            uint32_t so = row * 128 + ((q * 8) ^ ((row & 7) << 4));
            *reinterpret_cast<uint2*>(smem_c + so) =
                make_uint2(pack2(h0, h1), pack2(h2, h3));
            *reinterpret_cast<uint2*>(smem_c + ASZ + so) =
                make_uint2(pack2(l0, l1), pack2(l2, l3));
        }
        #pragma unroll
        for (int v = tid; v < NT * 8; v += THREADS) {
            int n = v >> 3, q = v & 7;
            size_t off = (size_t)(n0 + n) * KFULL + q * 8;
            uint32_t so = n * 128 + ((q * 16) ^ ((n & 7) << 4));
            *reinterpret_cast<uint4*>(smem_c + 2 * ASZ + so) =
                *reinterpret_cast<const uint4*>(Whi + off);
            *reinterpret_cast<uint4*>(smem_c + 2 * ASZ + BSZ + so) =
                *reinterpret_cast<const uint4*>(Wlo + off);
        }
        __syncthreads();
    } else if constexpr (NBUF == 2) {
        load_tiles(0, 0);
        cp_commit();
    }

    const uint32_t aSwz = (uint32_t)(lane & 7) << 4;
    const uint32_t kbBase = (uint32_t)(lane >> 4) << 4;
    uint32_t rowA[4], rowB[NL];
    #pragma unroll
    for (int mt = 0; mt < 4; ++mt)
        rowA[mt] = (uint32_t)(warpM * 64 + mt * 16 + (lane & 15)) * 128;
    #pragma unroll
    for (int c = 0; c < NL; ++c)
        rowB[c] = (uint32_t)(warpN * NH + c * 16 + (lane & 15)) * 128;

    for (int it = 0; it < NITER; ++it) {
        int buf;
        if constexpr (AF32) {
            buf = 0;
        } else if constexpr (NBUF == 1) {
            buf = 0;
            load_tiles(it, 0);
            cp_commit();
            CP_WAIT0();
            __syncthreads();
        } else {
            buf = it & 1;
            if (it + 1 < NITER) {
                load_tiles(it + 1, buf ^ 1);
                cp_commit();
                CP_WAIT1();
            } else {
                CP_WAIT0();
            }
            __syncthreads();
        }

        const uint32_t sAh = smem0 + buf * BUFB;
        const uint32_t sAl = sAh + ASZ;
        const uint32_t sBh = sAl + ASZ;
        const uint32_t sBl = sBh + BSZ;

        #pragma unroll
        for (int ks = 0; ks < 4; ++ks) {
            const uint32_t kb = ((uint32_t)(ks * 32) + kbBase) ^ aSwz;
            uint32_t ah[4][4], al[4][4];
            #pragma unroll
            for (int mt = 0; mt < 4; ++mt) {
                LDM4(ah[mt], sAh + rowA[mt] + kb);
                LDM4(al[mt], sAl + rowA[mt] + kb);
            }
            #pragma unroll
            for (int c = 0; c < NL; ++c) {
                uint32_t bh[4], bl[4];
                LDM4(bh, sBh + rowB[c] + kb);
                LDM4(bl, sBl + rowB[c] + kb);
                #pragma unroll
                for (int mt = 0; mt < 4; ++mt) {
                    MMA3(acc[mt][2 * c], acc[mt][2 * c + 1], ah[mt], al[mt], bh, bl);
                }
            }
        }
        if constexpr (!AF32) {
            if (NBUF == 1 || it + 1 < NITER) __syncthreads();
        }
    }

    const int tr = lane >> 2, tc = (lane & 3) * 2;
    #pragma unroll
    for (int mt = 0; mt < 4; ++mt)
        #pragma unroll
        for (int half = 0; half < 2; ++half) {
            const int m = m0 + warpM * 64 + mt * 16 + tr + half * 8;
            const int bb = m / LOUT;
            const int pp = m - bb * LOUT;
            #pragma unroll
            for (int nt = 0; nt < NI; ++nt) {
                const int n = n0 + warpN * NH + nt * 8 + tc;
                const float d0 = acc[mt][nt][half * 2 + 0];
                const float d1 = acc[mt][nt][half * 2 + 1];
                if constexpr (OUTMODE == 3) {
                    size_t o = (size_t)blockIdx.z * (2048 * 1024) +
                               (size_t)m * NS + n;
                    *reinterpret_cast<float2*>(Of32 + o) = make_float2(d0, d1);
                    continue;
                }
                float b0, b1;
                if constexpr (ROWBIAS) {
                    b0 = bias[(size_t)bb * 64 + n];
                    b1 = bias[(size_t)bb * 64 + n + 1];
                } else {
                    b0 = bias[n]; b1 = bias[n + 1];
                }
                const float v0 = fmaxf(d0 + b0, 0.f);
                const float v1 = fmaxf(d1 + b1, 0.f);
                size_t o;
                if constexpr (OUTMODE == 0) o = (size_t)m * NS + n;
                else o = (size_t)bb * 16640 + (size_t)pp * 256 + n;
                if constexpr (OUTF32) {
                    *reinterpret_cast<float2*>(Of32 + o) = make_float2(v0, v1);
                } else {
                    bf16 h0, h1, l0, l1;
                    split2(v0, h0, l0); split2(v1, h1, l1);
                    *reinterpret_cast<uint32_t*>(Ohi + o) = pack2(h0, h1);
                    *reinterpret_cast<uint32_t*>(Olo + o) = pack2(l0, l1);
                }
            }
        }
}

// ---------------------------------------------------------------------------
#define PREP_SA   4096
#define PREP_C1   (128 * 192)
#define PREP_C2   (256 * 384)
#define PREP_C3   (256 * 768)
#define PREP_WPT  4096
#define PREP_WB1  4096
#define PREP_WB2  8192
#define PREP_WB3  32768
#define PREP_SMALL (PREP_SA + PREP_C1 + PREP_C2 + PREP_C3 + PREP_WPT + \
                    PREP_WB1 + PREP_WB2 + PREP_WB3)

__global__ void prep_small_kernel(
    const float* __restrict__ Wp, const float* __restrict__ W1,
    const float* __restrict__ W2, const float* __restrict__ W3,
    const float* __restrict__ Wb1, const float* __restrict__ Wb2,
    const float* __restrict__ Wb3,
    bf16* wah, bf16* wal, bf16* w1h, bf16* w1l, bf16* w2h, bf16* w2l,
    bf16* w3h, bf16* w3l,
    float* wpt, float* wb1t, float* wb2t, float* wb3t)
{
    int idx = blockIdx.x * 256 + threadIdx.x;
    if (idx >= PREP_SMALL) return;
    bf16 h, l;
    if (idx < PREP_SA) {
        int p = idx >> 6, i = idx & 63;
        split2(Wp[p * 128 + i * 2 + 1], h, l);
        wah[idx] = h; wal[idx] = l; return;
    }
    idx -= PREP_SA;
    if (idx < PREP_C1) {
        int o = idx / 192, rem = idx - o * 192;
        int i = rem / 3, j = rem - i * 3;
        split2(W1[idx], h, l);
        w1h[o * 192 + j * 64 + i] = h; w1l[o * 192 + j * 64 + i] = l; return;
    }
    idx -= PREP_C1;
    if (idx < PREP_C2) {
        int o = idx / 384, rem = idx - o * 384;
        int i = rem / 3, j = rem - i * 3;
        split2(W2[idx], h, l);
        w2h[o * 384 + j * 128 + i] = h; w2l[o * 384 + j * 128 + i] = l; return;
    }
    idx -= PREP_C2;
    if (idx < PREP_C3) {
        int o = idx / 768, rem = idx - o * 768;
        int i = rem / 3, j = rem - i * 3;
        split2(W3[idx], h, l);
        w3h[o * 768 + j * 256 + i] = h; w3l[o * 768 + j * 256 + i] = l; return;
    }
    idx -= PREP_C3;
    if (idx < PREP_WPT) { int i = idx >> 6, p = idx & 63; wpt[idx] = Wp[p * 128 + i * 2]; return; }
    idx -= PREP_WPT;
    if (idx < PREP_WB1) { int i = idx >> 6, n = idx & 63; wb1t[idx] = Wb1[n * 64 + i]; return; }
    idx -= PREP_WB1;
    if (idx < PREP_WB2) { int i = idx >> 7, n = idx & 127; wb2t[idx] = Wb2[n * 64 + i]; return; }
    idx -= PREP_WB2;
    { int i = idx >> 8, n = idx & 255; wb3t[idx] = Wb3[n * 128 + i]; }
}

__global__ void __launch_bounds__(256) prep_fc_kernel(
    const float* __restrict__ Wfc1, bf16* __restrict__ wfh,
    bf16* __restrict__ wfl)
{
    extern __shared__ float s[];
    const int n = blockIdx.x, tid = threadIdx.x;
    const float* src = Wfc1 + (size_t)n * 16640;
    for (int k = tid; k < 16384; k += 256) {
        int c = k >> 6, p = k & 63;
        s[c * 65 + p] = src[k];
    }
    __syncthreads();
    bf16* dh = wfh + (size_t)n * 16640;
    bf16* dl = wfl + (size_t)n * 16640;
    for (int k2 = tid; k2 < 16384; k2 += 256) {
        int p = k2 >> 8, c = k2 & 255;
        bf16 h, l;
        split2(s[c * 65 + p], h, l);
        dh[k2] = h; dl[k2] = l;
    }
    for (int k2 = 16384 + tid; k2 < 16640; k2 += 256) {
        bf16 h, l;
        split2(src[k2], h, l);
        dh[k2] = h; dl[k2] = l;
    }
}

#define BB 16
__global__ void __launch_bounds__(256) branch_s0_kernel(
    const float* __restrict__ x,
    const float* __restrict__ wpt,  const float* __restrict__ bp,
    const float* __restrict__ wb1t, const float* __restrict__ bb1,
    const float* __restrict__ wb2t, const float* __restrict__ bb2,
    const float* __restrict__ wb3t, const float* __restrict__ bb3,
    float* __restrict__ s0, bf16* __restrict__ zh, bf16* __restrict__ zl)
{
    __shared__ float x0s[BB][64], f1s[BB][64], f2s[BB][128];
    const int tid = threadIdx.x;
    const int b0 = blockIdx.x * BB;
    #pragma unroll
    for (int t = 0; t < 4; ++t) {
        int idx = tid + t * 256;
        int bs = idx >> 6, i = idx & 63;
        x0s[bs][i] = x[(size_t)(b0 + bs) * 16384 + i];
    }
    __syncthreads();
    #pragma unroll
    for (int t = 0; t < 4; ++t) {
        int idx = tid + t * 256;
        int bs = idx >> 6, n = idx & 63;
        float a0 = bp[n], a1 = bb1[n];
        #pragma unroll 8
        for (int i = 0; i < 64; ++i) {
            float xv = x0s[bs][i];
            a0 += wpt[i * 64 + n] * xv;
            a1 += wb1t[i * 64 + n] * xv;
        }
        s0[(size_t)(b0 + bs) * 64 + n] = a0;
        f1s[bs][n] = fmaxf(a1, 0.f);
    }
    __syncthreads();
    #pragma unroll
    for (int t = 0; t < 8; ++t) {
        int idx = tid + t * 256;
        int bs = idx >> 7, n = idx & 127;
        float a = bb2[n];
        #pragma unroll 8
        for (int i = 0; i < 64; ++i) a += wb2t[i * 128 + n] * f1s[bs][i];
        f2s[bs][n] = fmaxf(a, 0.f);
    }
    __syncthreads();
    #pragma unroll
    for (int t = 0; t < 16; ++t) {
        int idx = tid + t * 256;
        int bs = idx >> 8, n = idx & 255;
        float a = bb3[n];
        #pragma unroll 8
        for (int i = 0; i < 128; ++i) a += wb3t[i * 256 + n] * f2s[bs][i];
        float v = fmaxf(a, 0.f);
        bf16 h, l;
        split2(v, h, l);
        size_t o = (size_t)(b0 + bs) * 16640 + 16384 + n;
        zh[o] = h; zl[o] = l;
    }
}

// fc2: sums 4 fc1 partials + bias + relu, then the 1024->2 dot.
__global__ void __launch_bounds__(128) fc2_kernel(
    const float* __restrict__ f1p, const float* __restrict__ bfc1,
    const float* __restrict__ W, const float* __restrict__ bias,
    float* __restrict__ out)
{
    __shared__ float red0[4], red1[4];
    const int b = blockIdx.x, tid = threadIdx.x;
    const float* p0 = f1p + (size_t)b * 1024;
    float s0 = 0.f, s1 = 0.f;
    for (int k = tid; k < 1024; k += 128) {
        float v = p0[k] + p0[(size_t)2048 * 1024 + k] +
                  p0[(size_t)2 * 2048 * 1024 + k] +
                  p0[(size_t)3 * 2048 * 1024 + k] + bfc1[k];
        v = fmaxf(v, 0.f);
        s0 += v * W[k];
        s1 += v * W[1024 + k];
    }
    #pragma unroll
    for (int off = 16; off > 0; off >>= 1) {
        s0 += __shfl_down_sync(0xffffffffu, s0, off);
        s1 += __shfl_down_sync(0xffffffffu, s1, off);
    }
    if ((tid & 31) == 0) { red0[tid >> 5] = s0; red1[tid >> 5] = s1; }
    __syncthreads();
    if (tid == 0) {
        out[b * 2 + 0] = red0[0] + red0[1] + red0[2] + red0[3] + bias[0];
        out[b * 2 + 1] = red1[0] + red1[1] + red1[2] + red1[3] + bias[1];
    }
}

// ---------------------------------------------------------------------------
extern "C" void kernel_launch(void* const* d_in, const int* in_sizes, int n_in,
                              void* d_out, int out_size)
{
    const float* x    = (const float*)d_in[0];
    const float* Wp   = (const float*)d_in[1];
    const float* bp   = (const float*)d_in[2];
    const float* W1   = (const float*)d_in[3];
    const float* b1   = (const float*)d_in[4];
    const float* W2   = (const float*)d_in[5];
    const float* b2   = (const float*)d_in[6];
    const float* W3   = (const float*)d_in[7];
    const float* b3   = (const float*)d_in[8];
    const float* Wb1  = (const float*)d_in[9];
    const float* bb1  = (const float*)d_in[10];
    const float* Wb2  = (const float*)d_in[11];
    const float* bb2  = (const float*)d_in[12];
    const float* Wb3  = (const float*)d_in[13];
    const float* bb3  = (const float*)d_in[14];
    const float* Wfc1 = (const float*)d_in[15];
    const float* bfc1 = (const float*)d_in[16];
    const float* Wfc2 = (const float*)d_in[17];
    const float* bfc2 = (const float*)d_in[18];
    float* out = (float*)d_out;

    static void *h0h, *h0l, *h1h, *h1l, *h2h, *h2l, *zh, *zl, *f1p, *s0;
    static void *wah, *wal, *w1h, *w1l, *w2h, *w2l, *w3h, *w3l, *wfh, *wfl;
    static void *wpt, *wb1t, *wb2t, *wb3t;
    static cudaStream_t s1;
    static cudaEvent_t evFork, evJoin;
    static bool init = false;
    if (!init) {
        cudaGetSymbolAddress(&h0h, g_h0h); cudaGetSymbolAddress(&h0l, g_h0l);
        cudaGetSymbolAddress(&h1h, g_h1h); cudaGetSymbolAddress(&h1l, g_h1l);
        cudaGetSymbolAddress(&h2h, g_h2h); cudaGetSymbolAddress(&h2l, g_h2l);
        cudaGetSymbolAddress(&zh,  g_zh);  cudaGetSymbolAddress(&zl,  g_zl);
        cudaGetSymbolAddress(&f1p, g_f1p); cudaGetSymbolAddress(&s0,  g_s0);
        cudaGetSymbolAddress(&wah, g_wah); cudaGetSymbolAddress(&wal, g_wal);
        cudaGetSymbolAddress(&w1h, g_w1h); cudaGetSymbolAddress(&w1l, g_w1l);
        cudaGetSymbolAddress(&w2h, g_w2h); cudaGetSymbolAddress(&w2l, g_w2l);
        cudaGetSymbolAddress(&w3h, g_w3h); cudaGetSymbolAddress(&w3l, g_w3l);
        cudaGetSymbolAddress(&wfh, g_wfh); cudaGetSymbolAddress(&wfl, g_wfl);
        cudaGetSymbolAddress(&wpt, g_wpt); cudaGetSymbolAddress(&wb1t, g_wb1t);
        cudaGetSymbolAddress(&wb2t, g_wb2t); cudaGetSymbolAddress(&wb3t, g_wb3t);
        cudaStreamCreateWithFlags(&s1, cudaStreamNonBlocking);
        cudaEventCreateWithFlags(&evFork, cudaEventDisableTiming);
        cudaEventCreateWithFlags(&evJoin, cudaEventDisableTiming);
        auto setsm = [](const void* f, int bytes) {
            cudaFuncSetAttribute(f, cudaFuncAttributeMaxDynamicSharedMemorySize, bytes);
        };
        setsm((const void*)gemm_kernel<64, 4, 2, 1, 64, 64, 64, 64, 256, 255, 1, 1, 0, 64, true, true, false>, 49152);
        setsm((const void*)gemm_kernel<128, 2, 2, 1, 192, 192, 128, 64, 255, 255, 1, -1, 0, 128, false, false, false>, 65536);
        setsm((const void*)gemm_kernel<256, 1, 2, 2, 384, 384, 256, 128, 255, 128, 2, -1, 0, 256, false, false, false>, 196608);
        setsm((const void*)gemm_kernel<256, 1, 2, 2, 768, 768, 256, 256, 128, 64, 2, -1, 2, 0, false, false, false>, 196608);
        setsm((const void*)gemm_kernel<256, 1, 2, 2, 4160, 16640, 256, 16640, 1, 1, 1, 0, 3, 1024, false, false, true>, 196608);
        setsm((const void*)prep_fc_kernel, 256 * 65 * 4);
        init = true;
    }

    // Fork: prep_fc runs on side stream, overlapped with the conv chain.
    cudaEventRecord(evFork, 0);
    cudaStreamWaitEvent(s1, evFork, 0);
    prep_fc_kernel<<<1024, 256, 256 * 65 * 4, s1>>>(Wfc1, (bf16*)wfh, (bf16*)wfl);
    cudaEventRecord(evJoin, s1);

    prep_small_kernel<<<(PREP_SMALL + 255) / 256, 256>>>(
        Wp, W1, W2, W3, Wb1, Wb2, Wb3,
        (bf16*)wah, (bf16*)wal, (bf16*)w1h, (bf16*)w1l, (bf16*)w2h, (bf16*)w2l,
        (bf16*)w3h, (bf16*)w3l,
        (float*)wpt, (float*)wb1t, (float*)wb2t, (float*)wb3t);

    branch_s0_kernel<<<2048 / BB, 256>>>(
        x, (const float*)wpt, bp, (const float*)wb1t, bb1,
        (const float*)wb2t, bb2, (const float*)wb3t, bb3,
        (float*)s0, (bf16*)zh, (bf16*)zl);

    // stage-A (R13 config)
    gemm_kernel<64, 4, 2, 1, 64, 64, 64, 64, 256, 255, 1, 1, 0, 64, true, true, false>
        <<<dim3(1, 4080), 64, 49152>>>(
            x, nullptr, nullptr, (const bf16*)wah, (const bf16*)wal,
            (const float*)s0, nullptr, (bf16*)h0h, (bf16*)h0l);

    // conv1 (R13 config)
    gemm_kernel<128, 2, 2, 1, 192, 192, 128, 64, 255, 255, 1, -1, 0, 128, false, false, false>
        <<<dim3(1, 4080), 128, 65536>>>(
            nullptr, (const bf16*)h0h, (const bf16*)h0l,
            (const bf16*)w1h, (const bf16*)w1l, b1,
            nullptr, (bf16*)h1h, (bf16*)h1l);

    // conv2 (R8 config)
    gemm_kernel<256, 1, 2, 2, 384, 384, 256, 128, 255, 128, 2, -1, 0, 256, false, false, false>
        <<<dim3(1, 2048), 256, 196608>>>(
            nullptr, (const bf16*)h1h, (const bf16*)h1l,
            (const bf16*)w2h, (const bf16*)w2l, b2,
            nullptr, (bf16*)h2h, (bf16*)h2l);

    // conv3 -> z (R8 config)
    gemm_kernel<256, 1, 2, 2, 768, 768, 256, 256, 128, 64, 2, -1, 2, 0, false, false, false>
        <<<dim3(1, 1024), 256, 196608>>>(
            nullptr, (const bf16*)h2h, (const bf16*)h2l,
            (const bf16*)w3h, (const bf16*)w3l, b3,
            nullptr, (bf16*)zh, (bf16*)zl);

    // Join: fc1 needs prep_fc's output.
    cudaStreamWaitEvent(0, evJoin, 0);

    // fc1: conv2-shaped (warp 64x64), 4-way k-split -> fp32 partials
    gemm_kernel<256, 1, 2, 2, 4160, 16640, 256, 16640, 1, 1, 1, 0, 3, 1024, false, false, true>
        <<<dim3(4, 16, 4), 256, 196608>>>(
            nullptr, (const bf16*)zh, (const bf16*)zl,
            (const bf16*)wfh, (const bf16*)wfl, nullptr,
            (float*)f1p, nullptr, nullptr);

    fc2_kernel<<<2048, 128>>>((const float*)f1p, bfc1, Wfc2, bfc2, out);
}